// round 10
// baseline (speedup 1.0000x reference)
#include <cuda_runtime.h>
#include <cuda_bf16.h>
#include <stdint.h>

// Fixed dataset: SUB_NO=64, T_HIST=200, T_DATA=100000, delta_spike=0
#define SUB    64
#define THIST  200
#define LCH    25                 // chunk length; divides THIST
#define OLDC   (THIST / LCH)      // 8 chunks back = t-200
#define NCPAD  4096               // padded chunk capacity (4 warp segments of 1024)
#define TCAP   (NCPAD * LCH)      // 102400
#define K2CH   2                  // chunks per k2c block (50 t rows)
#define K2ROWS (K2CH * LCH + THIST)   // 250 count rows staged

// Device scratch (zero-initialized at module load; never freed)
__device__ uint64_t        g_cmask[SUB];                     // unpermuted (for k1b)
__device__ __align__(16) uint8_t g_zc[(size_t)TCAP * SUB];   // spike counts Zc[t][s]
__device__ __nv_bfloat16   g_R[(size_t)TCAP * SUB];          // theta + Y@C^T (bf16)
__device__ float2          g_loc[3 * SUB][NCPAD];            // [b*64+s][c] local (Lu,Lv)
__device__ float           g_st[(size_t)NCPAD * SUB * 6];    // [c][s][b*2] exclusive (u,v)

// ---------------------------------------------------------------------------
// k1a: pack Z -> PERMUTED masks via float2+2 ballots (bit k <-> subunit 2k,
// bit 32+k <-> subunit 2k+1; popcount is permutation-invariant), per-chunk
// locals with register-recurrence weights, per-(t,s) byte counts.
// Block = 100 t rows = 4 chunks.
// ---------------------------------------------------------------------------
__global__ __launch_bounds__(256) void k1a_pack_local(
    const float* __restrict__ Z, const float* __restrict__ C,
    const float* __restrict__ tausp, int T, int NC)
{
    __shared__ uint64_t msh[104];
    __shared__ uint64_t Cm[SUB];          // PERMUTED masks (this kernel only)
    __shared__ float    s_inv[3], s_r[3];
    __shared__ float2   shloc[3 * SUB][4];
    __shared__ __align__(16) uint8_t scnt[100 * SUB];

    const int tid = threadIdx.x, lane = tid & 31, warp = tid >> 5;
    const long tb = (long)blockIdx.x * 100;

    // pack: one row per warp iteration; lane loads float2 (coalesced 256B row).
    // 13 independent iterations -> deep MLP.
    #pragma unroll
    for (int rr = 0; rr < 13; rr++) {
        int t = warp * 13 + rr;
        long gt = tb + t;
        bool valid = (t < 100) && (gt < T);
        float2 z = make_float2(0.f, 0.f);
        if (valid) z = ((const float2*)(Z + gt * SUB))[lane];
        unsigned m0 = __ballot_sync(0xffffffffu, z.x != 0.f);  // subunits 2k
        unsigned m1 = __ballot_sync(0xffffffffu, z.y != 0.f);  // subunits 2k+1
        if (lane == 0 && t < 100)
            msh[t] = (uint64_t)m0 | ((uint64_t)m1 << 32);
    }
    if (tid < SUB) {
        uint64_t m = 0, mp = 0;
        const float* cr = C + tid * SUB;
        #pragma unroll 8
        for (int j = 0; j < SUB; j++) {
            if (cr[j] != 0.0f) {
                m  |= 1ull << j;
                int pos = (j & 1) ? (32 + (j >> 1)) : (j >> 1);
                mp |= 1ull << pos;
            }
        }
        Cm[tid] = mp;
        if (blockIdx.x == 0) g_cmask[tid] = m;
    }
    if (tid < 3) {
        float inv = 1.0f / expf(tausp[tid]);
        s_inv[tid] = inv;
        s_r[tid]   = __expf(-inv);
    }
    __syncthreads();

    // locals + counts: thread = (chunk-in-block, s); weights via recurrence
    {
        const int cl = tid >> 6, s = tid & 63;
        const uint64_t cm = Cm[s];
        const float inv0 = s_inv[0], inv1 = s_inv[1], inv2 = s_inv[2];
        const float r0 = s_r[0], r1 = s_r[1], r2 = s_r[2];

        float w0 = 1.f, w1 = 1.f, w2 = 1.f;       // e^{-j/tau}
        float y0 = 0.f, y1 = 0.f, y2 = 0.f;       // (j/tau) e^{-j/tau}
        float lu0=0.f,lu1=0.f,lu2=0.f, lv0=0.f,lv1=0.f,lv2=0.f;
        const int rbase = cl * LCH + (LCH - 1);
        #pragma unroll
        for (int j = 0; j < LCH; j++) {
            int row = rbase - j;
            int cnti = __popcll(msh[row] & cm);
            scnt[row * SUB + s] = (uint8_t)cnti;
            float cnt = (float)cnti;
            lu0 = fmaf(w0, cnt, lu0);  lv0 = fmaf(y0, cnt, lv0);
            lu1 = fmaf(w1, cnt, lu1);  lv1 = fmaf(y1, cnt, lv1);
            lu2 = fmaf(w2, cnt, lu2);  lv2 = fmaf(y2, cnt, lv2);
            y0 = r0 * fmaf(inv0, w0, y0);  w0 *= r0;
            y1 = r1 * fmaf(inv1, w1, y1);  w1 *= r1;
            y2 = r2 * fmaf(inv2, w2, y2);  w2 *= r2;
        }
        shloc[s][cl]           = make_float2(lu0, lv0);
        shloc[SUB + s][cl]     = make_float2(lu1, lv1);
        shloc[2 * SUB + s][cl] = make_float2(lu2, lv2);
    }
    __syncthreads();

    #pragma unroll
    for (int idx = tid; idx < 100 * SUB / 16; idx += 256) {
        long row = tb + (idx >> 2);
        if (row < TCAP)
            ((int4*)(g_zc + row * SUB))[idx & 3] = ((const int4*)scnt)[idx];
    }
    if (tid < 3 * SUB) {
        #pragma unroll
        for (int k = 0; k < 4; k++) {
            int cc = blockIdx.x * 4 + k;
            if (cc < NC) g_loc[tid][cc] = shloc[tid][k];
        }
    }
}

// ---------------------------------------------------------------------------
// k2b: windowed scan — decay over 64 chunks < 1e-19; each warp scans its
// 1024-chunk segment independently after a 2-subtile warm-up.
// ---------------------------------------------------------------------------
__global__ __launch_bounds__(128) void k2b_scan(const float* __restrict__ tausp, int NC)
{
    const int plane = blockIdx.x;               // 0..191
    const int b = plane >> 6, s = plane & 63;
    const int warp = threadIdx.x >> 5, lane = threadIdx.x & 31;

    const float inv = 1.0f / expf(tausp[b]);
    const float dL  = (float)LCH * inv;
    float rho[5], del[5];
    #pragma unroll
    for (int k = 0; k < 5; k++) {
        float off = (float)(1 << k);
        rho[k] = __expf(-off * dL);
        del[k] = off * dL;
    }
    const float pl  = __expf(-(float)lane * dL);
    const float dl  = (float)lane * dL;
    const float r32 = __expf(-32.0f * dL);
    const float d32 = 32.0f * dL;

    const float2* pln = g_loc[plane];
    const int seg = warp * 1024;
    float cu = 0.f, cv = 0.f;

    #pragma unroll 2
    for (int ti = -2; ti < 32; ti++) {          // 2 warm-up subtiles (64 chunks)
        int c = seg + ti * 32 + lane;
        float2 l = (c >= 0) ? pln[c] : make_float2(0.f, 0.f);

        float au = l.x, av = l.y;
        #pragma unroll
        for (int kk = 0; kk < 5; kk++) {
            int off = 1 << kk;
            float ou = __shfl_up_sync(0xffffffffu, au, off);
            float ov = __shfl_up_sync(0xffffffffu, av, off);
            if (lane >= off) {
                av = fmaf(rho[kk], fmaf(del[kk], ou, ov), av);
                au = fmaf(rho[kk], ou, au);
            }
        }
        float exu = __shfl_up_sync(0xffffffffu, au, 1);
        float exv = __shfl_up_sync(0xffffffffu, av, 1);
        if (lane == 0) { exu = 0.f; exv = 0.f; }

        if (ti >= 0 && c < NC) {
            float su = fmaf(pl, cu, exu);
            float sv = fmaf(pl, fmaf(dl, cu, cv), exv);
            *(float2*)(g_st + ((size_t)c * SUB + s) * 6 + 2 * b) = make_float2(su, sv);
        }
        float iu = __shfl_sync(0xffffffffu, au, 31);
        float iv = __shfl_sync(0xffffffffu, av, 31);
        cv = fmaf(r32, fmaf(d32, cu, cv), iv);
        cu = fmaf(r32, cu, iu);
    }
}

// ---------------------------------------------------------------------------
// k1b: R = theta + Y@C^T (bf16). Reads only Y; masks from g_cmask.
// ---------------------------------------------------------------------------
__global__ __launch_bounds__(256) void k1b_rmat(
    const float* __restrict__ Y, const float* __restrict__ theta, int T)
{
    __shared__ float Ysh[32 * 65];
    __shared__ __nv_bfloat16 Xsh[32 * 66];
    __shared__ uint64_t Cm[SUB];

    const int tid = threadIdx.x, lane = tid & 31, warp = tid >> 5;
    const long tb = (long)blockIdx.x * 32;

    if (tid < SUB) Cm[tid] = g_cmask[tid];

    #pragma unroll
    for (int idx = tid; idx < 32 * SUB; idx += 256) {
        int t = idx >> 6;
        long gt = tb + t;
        Ysh[t * 65 + (idx & 63)] = (gt < T) ? Y[tb * SUB + idx] : 0.f;
    }
    __syncthreads();

    #pragma unroll
    for (int uu = 0; uu < 8; uu++) {
        int s = uu * 8 + warp;
        uint64_t m = Cm[s];
        float acc = __ldg(theta + s);
        while (m) {
            int j = __ffsll((long long)m) - 1;
            m &= m - 1;
            acc += Ysh[lane * 65 + j];
        }
        Xsh[lane * 66 + s] = __float2bfloat16(acc);
    }
    __syncthreads();

    #pragma unroll
    for (int idx = tid; idx < 32 * SUB; idx += 256) {
        int t = idx >> 6, s = idx & 63;
        long gt = tb + t;
        if (gt < T)
            g_R[tb * SUB + idx] = Xsh[t * 66 + s];
    }
}

// ---------------------------------------------------------------------------
// k2c: main pass. thread = (chunk, s), 25 steps, init from scanned states.
// K2CH=2, 128-thr blocks, <=42 regs -> 12 blocks/SM (75% occ), grid 2000.
// Fully-unrolled steps==25 fast path.
// ---------------------------------------------------------------------------
__global__ void __launch_bounds__(128, 12) k2c_main(
    const float* __restrict__ S,
    const float* __restrict__ Vo, const float* __restrict__ W,
    const float* __restrict__ Ksp, const float* __restrict__ tausp,
    float* __restrict__ out, int T, int NC)
{
    __shared__ __align__(16) uint8_t scnt[K2ROWS * SUB];   // 16KB

    const int tid = threadIdx.x;
    const long tbt = (long)blockIdx.x * (K2CH * LCH);

    // stage count rows [tbt-200, tbt+50) as int4 (coalesced, zero-pad)
    #pragma unroll
    for (int idx = tid; idx < K2ROWS * SUB / 16; idx += 128) {
        long g = tbt - THIST + (idx >> 2);
        int4 v = make_int4(0, 0, 0, 0);
        if (g >= 0 && g < TCAP)
            v = ((const int4*)(g_zc + g * SUB))[idx & 3];
        ((int4*)scnt)[idx] = v;
    }
    __syncthreads();

    const int cl = tid >> 6, s = tid & 63;
    const int c = blockIdx.x * K2CH + cl;
    if (c >= NC) return;
    const long t0 = (long)c * LCH;
    const int steps = (T - t0 < (long)LCH) ? (int)(T - t0) : LCH;

    float inv0 = 1.0f / expf(tausp[0]);
    float inv1 = 1.0f / expf(tausp[1]);
    float inv2 = 1.0f / expf(tausp[2]);
    float r0 = __expf(-inv0), r1 = __expf(-inv1), r2 = __expf(-inv2);
    float e0 = __expf(-(float)THIST * inv0);
    float e1 = __expf(-(float)THIST * inv1);
    float e2 = __expf(-(float)THIST * inv2);
    float K0 = Ksp[s * 3 + 0], K1 = Ksp[s * 3 + 1], K2 = Ksp[s * 3 + 2];

    const float* pc = g_st + ((size_t)c * SUB + s) * 6;
    float2 a0 = *(const float2*)(pc + 0);
    float2 a1 = *(const float2*)(pc + 2);
    float2 a2 = *(const float2*)(pc + 4);
    float u0c = a0.x, v0c = a0.y, u1c = a1.x, v1c = a1.y, u2c = a2.x, v2c = a2.y;
    float u0o = 0.f, v0o = 0.f, u1o = 0.f, v1o = 0.f, u2o = 0.f, v2o = 0.f;
    if (c >= OLDC) {
        const float* po = g_st + ((size_t)(c - OLDC) * SUB + s) * 6;
        float2 b0 = *(const float2*)(po + 0);
        float2 b1 = *(const float2*)(po + 2);
        float2 b2 = *(const float2*)(po + 4);
        u0o = b0.x; v0o = b0.y; u1o = b1.x; v1o = b1.y; u2o = b2.x; v2o = b2.y;
    }

    const float vo = Vo[0];
    const float ws = W[s];
    const __nv_bfloat16* Rp = g_R + (size_t)t0 * SUB + s;
    const float* Sp = S + (size_t)t0 * SUB + s;
    float* op = out + (size_t)t0 * SUB + s;
    const uint8_t* cnew = scnt + (cl * LCH + THIST) * SUB + s;
    const uint8_t* cold = scnt + (cl * LCH) * SUB + s;

    if (e0 < 1e-8f && e1 < 1e-8f) {
        // Light path: only basis-2 truncation correction is numerically live.
        const float Kq2 = K2 * e2 * (float)THIST * inv2;
        const float Ke2 = K2 * e2;

        #define K2C_STEP(i)                                                         \
        {                                                                           \
            float filt = fmaf(K0, v0c, fmaf(K1, v1c, K2 * v2c));                    \
            filt = fmaf(-Kq2, u2o, filt);                                           \
            filt = fmaf(-Ke2, v2o, filt);                                           \
            float x = __bfloat162float(Rp[(size_t)(i) * SUB]) +                     \
                      Sp[(size_t)(i) * SUB] + filt;                                 \
            float sg = __fdividef(1.0f, 1.0f + __expf(-x));                         \
            op[(size_t)(i) * SUB] = fmaf(ws, sg, vo);                               \
            float zn = (float)(int)cnew[(i) * SUB];                                 \
            float zo = (float)(int)cold[(i) * SUB];                                 \
            v0c = r0 * fmaf(u0c, inv0, v0c);  u0c = fmaf(r0, u0c, zn);              \
            v1c = r1 * fmaf(u1c, inv1, v1c);  u1c = fmaf(r1, u1c, zn);              \
            v2c = r2 * fmaf(u2c, inv2, v2c);  u2c = fmaf(r2, u2c, zn);              \
            v2o = r2 * fmaf(u2o, inv2, v2o);  u2o = fmaf(r2, u2o, zo);              \
        }

        if (steps == LCH) {
            #pragma unroll
            for (int i = 0; i < LCH; i++) K2C_STEP(i)
        } else {
            for (int i = 0; i < steps; i++) K2C_STEP(i)
        }
        #undef K2C_STEP
    } else {
        // Full path (generic taus)
        float q0 = e0 * (float)THIST * inv0;
        float q1 = e1 * (float)THIST * inv1;
        float q2 = e2 * (float)THIST * inv2;
        for (int i = 0; i < steps; i++) {
            float tr0 = fmaf(-q0, u0o, v0c); tr0 = fmaf(-e0, v0o, tr0);
            float tr1 = fmaf(-q1, u1o, v1c); tr1 = fmaf(-e1, v1o, tr1);
            float tr2 = fmaf(-q2, u2o, v2c); tr2 = fmaf(-e2, v2o, tr2);
            float filt = fmaf(K0, tr0, fmaf(K1, tr1, K2 * tr2));

            float x = __bfloat162float(Rp[(size_t)i * SUB]) + Sp[(size_t)i * SUB] + filt;
            float sg = __fdividef(1.0f, 1.0f + __expf(-x));
            op[(size_t)i * SUB] = fmaf(ws, sg, vo);

            float zn = (float)(int)cnew[i * SUB];
            float zo = (float)(int)cold[i * SUB];
            v0c = r0 * fmaf(u0c, inv0, v0c);  u0c = fmaf(r0, u0c, zn);
            v0o = r0 * fmaf(u0o, inv0, v0o);  u0o = fmaf(r0, u0o, zo);
            v1c = r1 * fmaf(u1c, inv1, v1c);  u1c = fmaf(r1, u1c, zn);
            v1o = r1 * fmaf(u1o, inv1, v1o);  u1o = fmaf(r1, u1o, zo);
            v2c = r2 * fmaf(u2c, inv2, v2c);  u2c = fmaf(r2, u2c, zn);
            v2o = r2 * fmaf(u2o, inv2, v2o);  u2o = fmaf(r2, u2o, zo);
        }
    }
}

// ---------------------------------------------------------------------------
extern "C" void kernel_launch(void* const* d_in, const int* in_sizes, int n_in,
                              void* d_out, int out_size)
{
    const float* S     = (const float*)d_in[0];
    const float* Y     = (const float*)d_in[1];
    const float* Z     = (const float*)d_in[2];
    const float* C     = (const float*)d_in[3];
    const float* Vo    = (const float*)d_in[4];
    const float* W     = (const float*)d_in[5];
    const float* theta = (const float*)d_in[6];
    const float* Ksp   = (const float*)d_in[7];
    const float* tausp = (const float*)d_in[8];
    float* out = (float*)d_out;

    int T = in_sizes[0] / SUB;
    if (T > TCAP) T = TCAP;
    const int NC = (T + LCH - 1) / LCH;

    const int g1 = (T + 99) / 100;
    k1a_pack_local<<<g1, 256>>>(Z, C, tausp, T, NC);

    const int gB = (T + 31) / 32;
    k1b_rmat<<<gB, 256>>>(Y, theta, T);

    k2b_scan<<<3 * SUB, 128>>>(tausp, NC);

    const int gC = (NC + K2CH - 1) / K2CH;
    k2c_main<<<gC, 128>>>(S, Vo, W, Ksp, tausp, out, T, NC);
}

// round 11
// speedup vs baseline: 1.0322x; 1.0322x over previous
#include <cuda_runtime.h>
#include <cuda_bf16.h>
#include <stdint.h>

// Fixed dataset: SUB_NO=64, T_HIST=200, T_DATA=100000, delta_spike=0
#define SUB    64
#define THIST  200
#define LCH    25                 // chunk length; divides THIST
#define OLDC   (THIST / LCH)      // 8 chunks back = t-200
#define NCPAD  4096               // padded chunk capacity (4 warp segments of 1024)
#define TCAP   (NCPAD * LCH)      // 102400
#define K2CH   2                  // chunks per k2c block (50 t rows)

// Device scratch (zero-initialized at module load; never freed)
__device__ uint64_t        g_cmask[SUB];                     // unpermuted (for k1b)
__device__ __align__(16) uint8_t g_zc[(size_t)TCAP * SUB];   // spike counts Zc[t][s]
__device__ __nv_bfloat16   g_B[(size_t)TCAP * SUB];          // S + theta + Y@C^T (bf16)
__device__ float2          g_loc[3 * SUB][NCPAD];            // [b*64+s][c] local (Lu,Lv)
__device__ float           g_st[(size_t)NCPAD * SUB * 6];    // [c][s][b*2] exclusive (u,v)

// ---------------------------------------------------------------------------
// k1a: pack Z -> PERMUTED masks via float2+2 ballots (bit k <-> subunit 2k,
// bit 32+k <-> subunit 2k+1; popcount is permutation-invariant). Per-chunk
// locals via register-recurrence weights. Counts stored DIRECTLY to global
// (coalesced 32B/warp byte stores; no shared staging).
// Block = 100 t rows = 4 chunks.
// ---------------------------------------------------------------------------
__global__ __launch_bounds__(256) void k1a_pack_local(
    const float* __restrict__ Z, const float* __restrict__ C,
    const float* __restrict__ tausp, int T, int NC)
{
    __shared__ uint64_t msh[104];
    __shared__ uint64_t Cm[SUB];          // PERMUTED masks (this kernel only)
    __shared__ float    s_inv[3], s_r[3];
    __shared__ float2   shloc[3 * SUB][4];

    const int tid = threadIdx.x, lane = tid & 31, warp = tid >> 5;
    const long tb = (long)blockIdx.x * 100;

    // pack: one row per warp iteration; lane loads float2 (coalesced 256B row)
    #pragma unroll
    for (int rr = 0; rr < 13; rr++) {
        int t = warp * 13 + rr;
        long gt = tb + t;
        bool valid = (t < 100) && (gt < T);
        float2 z = make_float2(0.f, 0.f);
        if (valid) z = ((const float2*)(Z + gt * SUB))[lane];
        unsigned m0 = __ballot_sync(0xffffffffu, z.x != 0.f);  // subunits 2k
        unsigned m1 = __ballot_sync(0xffffffffu, z.y != 0.f);  // subunits 2k+1
        if (lane == 0 && t < 100)
            msh[t] = (uint64_t)m0 | ((uint64_t)m1 << 32);
    }
    if (tid < SUB) {
        uint64_t m = 0, mp = 0;
        const float* cr = C + tid * SUB;
        #pragma unroll 8
        for (int j = 0; j < SUB; j++) {
            if (cr[j] != 0.0f) {
                m  |= 1ull << j;
                int pos = (j & 1) ? (32 + (j >> 1)) : (j >> 1);
                mp |= 1ull << pos;
            }
        }
        Cm[tid] = mp;
        if (blockIdx.x == 0) g_cmask[tid] = m;
    }
    if (tid < 3) {
        float inv = 1.0f / expf(tausp[tid]);
        s_inv[tid] = inv;
        s_r[tid]   = __expf(-inv);
    }
    __syncthreads();

    // locals + direct count stores: thread = (chunk-in-block, s)
    {
        const int cl = tid >> 6, s = tid & 63;
        const uint64_t cm = Cm[s];
        const float inv0 = s_inv[0], inv1 = s_inv[1], inv2 = s_inv[2];
        const float r0 = s_r[0], r1 = s_r[1], r2 = s_r[2];

        float w0 = 1.f, w1 = 1.f, w2 = 1.f;       // e^{-j/tau}
        float y0 = 0.f, y1 = 0.f, y2 = 0.f;       // (j/tau) e^{-j/tau}
        float lu0=0.f,lu1=0.f,lu2=0.f, lv0=0.f,lv1=0.f,lv2=0.f;
        const int rbase = cl * LCH + (LCH - 1);
        uint8_t* zcp = g_zc + (tb + rbase) * SUB + s;
        #pragma unroll
        for (int j = 0; j < LCH; j++) {
            int row = rbase - j;
            int cnti = __popcll(msh[row] & cm);
            zcp[-(long)j * SUB] = (uint8_t)cnti;   // coalesced 32B/warp STG.U8
            float cnt = (float)cnti;
            lu0 = fmaf(w0, cnt, lu0);  lv0 = fmaf(y0, cnt, lv0);
            lu1 = fmaf(w1, cnt, lu1);  lv1 = fmaf(y1, cnt, lv1);
            lu2 = fmaf(w2, cnt, lu2);  lv2 = fmaf(y2, cnt, lv2);
            y0 = r0 * fmaf(inv0, w0, y0);  w0 *= r0;
            y1 = r1 * fmaf(inv1, w1, y1);  w1 *= r1;
            y2 = r2 * fmaf(inv2, w2, y2);  w2 *= r2;
        }
        shloc[s][cl]           = make_float2(lu0, lv0);
        shloc[SUB + s][cl]     = make_float2(lu1, lv1);
        shloc[2 * SUB + s][cl] = make_float2(lu2, lv2);
    }
    __syncthreads();

    if (tid < 3 * SUB) {
        #pragma unroll
        for (int k = 0; k < 4; k++) {
            int cc = blockIdx.x * 4 + k;
            if (cc < NC) g_loc[tid][cc] = shloc[tid][k];
        }
    }
}

// ---------------------------------------------------------------------------
// k2b: windowed scan — decay over 64 chunks < 1e-19; each warp scans its
// 1024-chunk segment independently after a 2-subtile warm-up.
// ---------------------------------------------------------------------------
__global__ __launch_bounds__(128) void k2b_scan(const float* __restrict__ tausp, int NC)
{
    const int plane = blockIdx.x;               // 0..191
    const int b = plane >> 6, s = plane & 63;
    const int warp = threadIdx.x >> 5, lane = threadIdx.x & 31;

    const float inv = 1.0f / expf(tausp[b]);
    const float dL  = (float)LCH * inv;
    float rho[5], del[5];
    #pragma unroll
    for (int k = 0; k < 5; k++) {
        float off = (float)(1 << k);
        rho[k] = __expf(-off * dL);
        del[k] = off * dL;
    }
    const float pl  = __expf(-(float)lane * dL);
    const float dl  = (float)lane * dL;
    const float r32 = __expf(-32.0f * dL);
    const float d32 = 32.0f * dL;

    const float2* pln = g_loc[plane];
    const int seg = warp * 1024;
    float cu = 0.f, cv = 0.f;

    #pragma unroll 2
    for (int ti = -2; ti < 32; ti++) {          // 2 warm-up subtiles (64 chunks)
        int c = seg + ti * 32 + lane;
        float2 l = (c >= 0) ? pln[c] : make_float2(0.f, 0.f);

        float au = l.x, av = l.y;
        #pragma unroll
        for (int kk = 0; kk < 5; kk++) {
            int off = 1 << kk;
            float ou = __shfl_up_sync(0xffffffffu, au, off);
            float ov = __shfl_up_sync(0xffffffffu, av, off);
            if (lane >= off) {
                av = fmaf(rho[kk], fmaf(del[kk], ou, ov), av);
                au = fmaf(rho[kk], ou, au);
            }
        }
        float exu = __shfl_up_sync(0xffffffffu, au, 1);
        float exv = __shfl_up_sync(0xffffffffu, av, 1);
        if (lane == 0) { exu = 0.f; exv = 0.f; }

        if (ti >= 0 && c < NC) {
            float su = fmaf(pl, cu, exu);
            float sv = fmaf(pl, fmaf(dl, cu, cv), exv);
            *(float2*)(g_st + ((size_t)c * SUB + s) * 6 + 2 * b) = make_float2(su, sv);
        }
        float iu = __shfl_sync(0xffffffffu, au, 31);
        float iv = __shfl_sync(0xffffffffu, av, 31);
        cv = fmaf(r32, fmaf(d32, cu, cv), iv);
        cu = fmaf(r32, cu, iu);
    }
}

// ---------------------------------------------------------------------------
// k1b: B = S + theta + Y@C^T (bf16) — R6 semantics; masks from g_cmask.
// ---------------------------------------------------------------------------
__global__ __launch_bounds__(256) void k1b_bmat(
    const float* __restrict__ S, const float* __restrict__ Y,
    const float* __restrict__ theta, int T)
{
    __shared__ float Ysh[32 * 65];
    __shared__ float Xsh[32 * 65];
    __shared__ uint64_t Cm[SUB];

    const int tid = threadIdx.x, lane = tid & 31, warp = tid >> 5;
    const long tb = (long)blockIdx.x * 32;

    if (tid < SUB) Cm[tid] = g_cmask[tid];

    #pragma unroll
    for (int idx = tid; idx < 32 * SUB; idx += 256) {
        int t = idx >> 6;
        long gt = tb + t;
        Ysh[t * 65 + (idx & 63)] = (gt < T) ? Y[tb * SUB + idx] : 0.f;
    }
    __syncthreads();

    // warp per s, lanes = t (uniform bit loop, conflict-free LDS)
    #pragma unroll
    for (int uu = 0; uu < 8; uu++) {
        int s = uu * 8 + warp;
        uint64_t m = Cm[s];
        float acc = __ldg(theta + s);
        while (m) {
            int j = __ffsll((long long)m) - 1;
            m &= m - 1;
            acc += Ysh[lane * 65 + j];
        }
        Xsh[lane * 65 + s] = acc;
    }
    __syncthreads();

    #pragma unroll
    for (int idx = tid; idx < 32 * SUB; idx += 256) {
        int t = idx >> 6, s = idx & 63;
        long gt = tb + t;
        if (gt < T) {
            float x = Xsh[t * 65 + s] + S[tb * SUB + idx];
            g_B[tb * SUB + idx] = __float2bfloat16(x);
        }
    }
}

// ---------------------------------------------------------------------------
// k2c: main pass. thread = (chunk, s), 25 steps, init from scanned states.
// ZERO shared memory: counts read directly from L2-resident g_zc (LDG.U8,
// hoisted by the full unroll), single bf16 B load per step.
// ---------------------------------------------------------------------------
__global__ void __launch_bounds__(128, 12) k2c_main(
    const float* __restrict__ Vo, const float* __restrict__ W,
    const float* __restrict__ Ksp, const float* __restrict__ tausp,
    float* __restrict__ out, int T, int NC)
{
    const int tid = threadIdx.x;
    const int cl = tid >> 6, s = tid & 63;
    const int c = blockIdx.x * K2CH + cl;
    if (c >= NC) return;
    const long t0 = (long)c * LCH;
    const int steps = (T - t0 < (long)LCH) ? (int)(T - t0) : LCH;

    float inv0 = 1.0f / expf(tausp[0]);
    float inv1 = 1.0f / expf(tausp[1]);
    float inv2 = 1.0f / expf(tausp[2]);
    float r0 = __expf(-inv0), r1 = __expf(-inv1), r2 = __expf(-inv2);
    float e0 = __expf(-(float)THIST * inv0);
    float e1 = __expf(-(float)THIST * inv1);
    float e2 = __expf(-(float)THIST * inv2);
    float K0 = Ksp[s * 3 + 0], K1 = Ksp[s * 3 + 1], K2 = Ksp[s * 3 + 2];

    const float* pc = g_st + ((size_t)c * SUB + s) * 6;
    float2 a0 = *(const float2*)(pc + 0);
    float2 a1 = *(const float2*)(pc + 2);
    float2 a2 = *(const float2*)(pc + 4);
    float u0c = a0.x, v0c = a0.y, u1c = a1.x, v1c = a1.y, u2c = a2.x, v2c = a2.y;
    float u0o = 0.f, v0o = 0.f, u1o = 0.f, v1o = 0.f, u2o = 0.f, v2o = 0.f;
    const bool has_old = (c >= OLDC);
    if (has_old) {
        const float* po = g_st + ((size_t)(c - OLDC) * SUB + s) * 6;
        float2 b0 = *(const float2*)(po + 0);
        float2 b1 = *(const float2*)(po + 2);
        float2 b2 = *(const float2*)(po + 4);
        u0o = b0.x; v0o = b0.y; u1o = b1.x; v1o = b1.y; u2o = b2.x; v2o = b2.y;
    }

    const float vo = Vo[0];
    const float ws = W[s];
    const __nv_bfloat16* Bp = g_B + (size_t)t0 * SUB + s;
    float* op = out + (size_t)t0 * SUB + s;
    const uint8_t* cnew = g_zc + (size_t)t0 * SUB + s;
    // For c < OLDC, t0+24 <= 199 < 200, so ALL old counts are exactly zero.
    const uint8_t* cold = has_old ? (g_zc + (size_t)(t0 - THIST) * SUB + s) : (const uint8_t*)0;

    if (e0 < 1e-8f && e1 < 1e-8f) {
        // Light path: only basis-2 truncation correction is numerically live.
        const float Kq2 = K2 * e2 * (float)THIST * inv2;
        const float Ke2 = K2 * e2;

        #define K2C_STEP(i)                                                         \
        {                                                                           \
            float filt = fmaf(K0, v0c, fmaf(K1, v1c, K2 * v2c));                    \
            filt = fmaf(-Kq2, u2o, filt);                                           \
            filt = fmaf(-Ke2, v2o, filt);                                           \
            float x = __bfloat162float(Bp[(size_t)(i) * SUB]) + filt;               \
            float sg = __fdividef(1.0f, 1.0f + __expf(-x));                         \
            op[(size_t)(i) * SUB] = fmaf(ws, sg, vo);                               \
            float zn = (float)(int)cnew[(size_t)(i) * SUB];                         \
            float zo = cold ? (float)(int)cold[(size_t)(i) * SUB] : 0.f;            \
            v0c = r0 * fmaf(u0c, inv0, v0c);  u0c = fmaf(r0, u0c, zn);              \
            v1c = r1 * fmaf(u1c, inv1, v1c);  u1c = fmaf(r1, u1c, zn);              \
            v2c = r2 * fmaf(u2c, inv2, v2c);  u2c = fmaf(r2, u2c, zn);              \
            v2o = r2 * fmaf(u2o, inv2, v2o);  u2o = fmaf(r2, u2o, zo);              \
        }

        if (steps == LCH) {
            #pragma unroll
            for (int i = 0; i < LCH; i++) K2C_STEP(i)
        } else {
            for (int i = 0; i < steps; i++) K2C_STEP(i)
        }
        #undef K2C_STEP
    } else {
        // Full path (generic taus)
        float q0 = e0 * (float)THIST * inv0;
        float q1 = e1 * (float)THIST * inv1;
        float q2 = e2 * (float)THIST * inv2;
        for (int i = 0; i < steps; i++) {
            float tr0 = fmaf(-q0, u0o, v0c); tr0 = fmaf(-e0, v0o, tr0);
            float tr1 = fmaf(-q1, u1o, v1c); tr1 = fmaf(-e1, v1o, tr1);
            float tr2 = fmaf(-q2, u2o, v2c); tr2 = fmaf(-e2, v2o, tr2);
            float filt = fmaf(K0, tr0, fmaf(K1, tr1, K2 * tr2));

            float x = __bfloat162float(Bp[(size_t)i * SUB]) + filt;
            float sg = __fdividef(1.0f, 1.0f + __expf(-x));
            op[(size_t)i * SUB] = fmaf(ws, sg, vo);

            float zn = (float)(int)cnew[(size_t)i * SUB];
            float zo = cold ? (float)(int)cold[(size_t)i * SUB] : 0.f;
            v0c = r0 * fmaf(u0c, inv0, v0c);  u0c = fmaf(r0, u0c, zn);
            v0o = r0 * fmaf(u0o, inv0, v0o);  u0o = fmaf(r0, u0o, zo);
            v1c = r1 * fmaf(u1c, inv1, v1c);  u1c = fmaf(r1, u1c, zn);
            v1o = r1 * fmaf(u1o, inv1, v1o);  u1o = fmaf(r1, u1o, zo);
            v2c = r2 * fmaf(u2c, inv2, v2c);  u2c = fmaf(r2, u2c, zn);
            v2o = r2 * fmaf(u2o, inv2, v2o);  u2o = fmaf(r2, u2o, zo);
        }
    }
}

// ---------------------------------------------------------------------------
extern "C" void kernel_launch(void* const* d_in, const int* in_sizes, int n_in,
                              void* d_out, int out_size)
{
    const float* S     = (const float*)d_in[0];
    const float* Y     = (const float*)d_in[1];
    const float* Z     = (const float*)d_in[2];
    const float* C     = (const float*)d_in[3];
    const float* Vo    = (const float*)d_in[4];
    const float* W     = (const float*)d_in[5];
    const float* theta = (const float*)d_in[6];
    const float* Ksp   = (const float*)d_in[7];
    const float* tausp = (const float*)d_in[8];
    float* out = (float*)d_out;

    int T = in_sizes[0] / SUB;
    if (T > TCAP) T = TCAP;
    const int NC = (T + LCH - 1) / LCH;

    const int g1 = (T + 99) / 100;
    k1a_pack_local<<<g1, 256>>>(Z, C, tausp, T, NC);

    const int gB = (T + 31) / 32;
    k1b_bmat<<<gB, 256>>>(S, Y, theta, T);

    k2b_scan<<<3 * SUB, 128>>>(tausp, NC);

    const int gC = (NC + K2CH - 1) / K2CH;
    k2c_main<<<gC, 128>>>(Vo, W, Ksp, tausp, out, T, NC);
}

// round 12
// speedup vs baseline: 1.2099x; 1.1721x over previous
#include <cuda_runtime.h>
#include <cuda_bf16.h>
#include <stdint.h>

// Fixed dataset: SUB_NO=64, T_HIST=200, T_DATA=100000, delta_spike=0
#define SUB    64
#define THIST  200
#define LCH    25                 // chunk length; divides THIST
#define OLDC   (THIST / LCH)      // 8 chunks back = t-200
#define NCPAD  4096               // padded chunk capacity (4 warp segments of 1024)
#define TCAP   (NCPAD * LCH)      // 102400
#define K2CH   4                  // chunks per k2c block (100 t rows)
#define K2ROWS (K2CH * LCH + THIST)   // 300 count rows staged

// Device scratch (zero-initialized at module load; never freed)
__device__ __align__(16) uint8_t g_zc[(size_t)TCAP * SUB];   // spike counts Zc[t][s]
__device__ __nv_bfloat16   g_B[(size_t)TCAP * SUB];          // S + theta + Y@C^T (bf16)
__device__ float2          g_loc[3 * SUB][NCPAD];            // [b*64+s][c] local (Lu,Lv)
__device__ float           g_st[(size_t)NCPAD * SUB * 6];    // [c][s][b*2] exclusive (u,v)

// ---------------------------------------------------------------------------
// kA (block-specialized): blocks [0,gA) run branch A (spike side), blocks
// [gA, gA+gB) run branch B (B-matrix side). The two phases read disjoint
// inputs and overlap across SMs in a single launch.
//
// Branch A (per 100 t rows): float2-ballot pack of Z into PERMUTED masks
// (bit k <-> subunit 2k, bit 32+k <-> 2k+1; popcount is perm-invariant),
// ballot-built permuted C masks, per-chunk locals via register-recurrence
// weights, counts stored directly to g_zc (coalesced 32B/warp STG.U8).
//
// Branch B (per 64 t rows): ballot-built unpermuted C masks, bit-gather
// raw = Y@C^T in shared, B = S + theta + raw stored bf16.
// ---------------------------------------------------------------------------
__global__ __launch_bounds__(256) void kA_combined(
    const float* __restrict__ S, const float* __restrict__ Y,
    const float* __restrict__ Z, const float* __restrict__ C,
    const float* __restrict__ theta, const float* __restrict__ tausp,
    int T, int NC, int gA)
{
    __shared__ __align__(16) char smbuf[33792];

    const int tid = threadIdx.x, lane = tid & 31, warp = tid >> 5;

    if ((int)blockIdx.x < gA) {
        // ================= Branch A: spike side =================
        uint64_t* msh   = (uint64_t*)(smbuf);          // 104 * 8 = 832
        uint64_t* CmA   = (uint64_t*)(smbuf + 832);    // 64 * 8 = 512
        float2  (*shloc)[4] = (float2(*)[4])(smbuf + 1344);  // 192*4*8 = 6144
        float*   s_cst  = (float*)(smbuf + 7488);      // 6 floats

        const long tb = (long)blockIdx.x * 100;

        // permuted C masks via float2 ballots (warp sweeps one C row)
        #pragma unroll
        for (int ss = 0; ss < 8; ss++) {
            int s = warp * 8 + ss;
            float2 cv = ((const float2*)(C + s * SUB))[lane];
            unsigned m0 = __ballot_sync(0xffffffffu, cv.x != 0.f);  // subunits 2k
            unsigned m1 = __ballot_sync(0xffffffffu, cv.y != 0.f);  // subunits 2k+1
            if (lane == 0) CmA[s] = (uint64_t)m0 | ((uint64_t)m1 << 32);
        }
        // pack Z rows (permuted bit order matching CmA)
        #pragma unroll
        for (int rr = 0; rr < 13; rr++) {
            int t = warp * 13 + rr;
            long gt = tb + t;
            bool valid = (t < 100) && (gt < T);
            float2 z = make_float2(0.f, 0.f);
            if (valid) z = ((const float2*)(Z + gt * SUB))[lane];
            unsigned m0 = __ballot_sync(0xffffffffu, z.x != 0.f);
            unsigned m1 = __ballot_sync(0xffffffffu, z.y != 0.f);
            if (lane == 0 && t < 100)
                msh[t] = (uint64_t)m0 | ((uint64_t)m1 << 32);
        }
        if (tid < 3) {
            float inv = 1.0f / expf(tausp[tid]);
            s_cst[tid]     = inv;
            s_cst[3 + tid] = __expf(-inv);
        }
        __syncthreads();

        // locals + direct count stores: thread = (chunk-in-block, s)
        {
            const int cl = tid >> 6, s = tid & 63;
            const uint64_t cm = CmA[s];
            const float inv0 = s_cst[0], inv1 = s_cst[1], inv2 = s_cst[2];
            const float r0 = s_cst[3], r1 = s_cst[4], r2 = s_cst[5];

            float w0 = 1.f, w1 = 1.f, w2 = 1.f;
            float y0 = 0.f, y1 = 0.f, y2 = 0.f;
            float lu0=0.f,lu1=0.f,lu2=0.f, lv0=0.f,lv1=0.f,lv2=0.f;
            const int rbase = cl * LCH + (LCH - 1);
            uint8_t* zcp = g_zc + (tb + rbase) * SUB + s;
            #pragma unroll
            for (int j = 0; j < LCH; j++) {
                int row = rbase - j;
                int cnti = __popcll(msh[row] & cm);
                zcp[-(long)j * SUB] = (uint8_t)cnti;   // coalesced STG.U8
                float cnt = (float)cnti;
                lu0 = fmaf(w0, cnt, lu0);  lv0 = fmaf(y0, cnt, lv0);
                lu1 = fmaf(w1, cnt, lu1);  lv1 = fmaf(y1, cnt, lv1);
                lu2 = fmaf(w2, cnt, lu2);  lv2 = fmaf(y2, cnt, lv2);
                y0 = r0 * fmaf(inv0, w0, y0);  w0 *= r0;
                y1 = r1 * fmaf(inv1, w1, y1);  w1 *= r1;
                y2 = r2 * fmaf(inv2, w2, y2);  w2 *= r2;
            }
            shloc[s][cl]           = make_float2(lu0, lv0);
            shloc[SUB + s][cl]     = make_float2(lu1, lv1);
            shloc[2 * SUB + s][cl] = make_float2(lu2, lv2);
        }
        __syncthreads();

        if (tid < 3 * SUB) {
            #pragma unroll
            for (int k = 0; k < 4; k++) {
                int cc = blockIdx.x * 4 + k;
                if (cc < NC) g_loc[tid][cc] = shloc[tid][k];
            }
        }
    } else {
        // ================= Branch B: B-matrix side =================
        float*    Ysh = (float*)(smbuf);               // 64*65*4 = 16640
        float*    Xsh = (float*)(smbuf + 16640);       // 64*65*4 = 16640
        uint64_t* CmB = (uint64_t*)(smbuf + 33280);    // 512

        const long tb = (long)(blockIdx.x - gA) * 64;

        // unpermuted C masks via scalar ballots
        #pragma unroll
        for (int ss = 0; ss < 8; ss++) {
            int s = warp * 8 + ss;
            float c0 = C[s * SUB + lane];
            float c1 = C[s * SUB + 32 + lane];
            unsigned m0 = __ballot_sync(0xffffffffu, c0 != 0.f);
            unsigned m1 = __ballot_sync(0xffffffffu, c1 != 0.f);
            if (lane == 0) CmB[s] = (uint64_t)m0 | ((uint64_t)m1 << 32);
        }
        // stage Y tile (coalesced)
        #pragma unroll
        for (int idx = tid; idx < 64 * SUB; idx += 256) {
            int t = idx >> 6;
            long gt = tb + t;
            Ysh[t * 65 + (idx & 63)] = (gt < T) ? Y[tb * SUB + idx] : 0.f;
        }
        __syncthreads();

        // bit-gather raw+theta: warp per s, lanes sweep t (2 halves of 64)
        #pragma unroll
        for (int uu = 0; uu < 8; uu++) {
            int s = uu * 8 + warp;
            uint64_t m0 = CmB[s];
            float th = __ldg(theta + s);
            #pragma unroll
            for (int half = 0; half < 2; half++) {
                int t = half * 32 + lane;
                float acc = th;
                uint64_t m = m0;
                while (m) {
                    int j = __ffsll((long long)m) - 1;
                    m &= m - 1;
                    acc += Ysh[t * 65 + j];
                }
                Xsh[t * 65 + s] = acc;
            }
        }
        __syncthreads();

        // B = raw + theta + S, bf16, coalesced
        #pragma unroll
        for (int idx = tid; idx < 64 * SUB; idx += 256) {
            int t = idx >> 6, s = idx & 63;
            long gt = tb + t;
            if (gt < T) {
                float x = Xsh[t * 65 + s] + S[tb * SUB + idx];
                g_B[tb * SUB + idx] = __float2bfloat16(x);
            }
        }
    }
}

// ---------------------------------------------------------------------------
// k2b: windowed scan — decay over 64 chunks < 1e-19; each warp scans its
// 1024-chunk segment independently after a 2-subtile warm-up.
// ---------------------------------------------------------------------------
__global__ __launch_bounds__(128) void k2b_scan(const float* __restrict__ tausp, int NC)
{
    const int plane = blockIdx.x;               // 0..191
    const int b = plane >> 6, s = plane & 63;
    const int warp = threadIdx.x >> 5, lane = threadIdx.x & 31;

    const float inv = 1.0f / expf(tausp[b]);
    const float dL  = (float)LCH * inv;
    float rho[5], del[5];
    #pragma unroll
    for (int k = 0; k < 5; k++) {
        float off = (float)(1 << k);
        rho[k] = __expf(-off * dL);
        del[k] = off * dL;
    }
    const float pl  = __expf(-(float)lane * dL);
    const float dl  = (float)lane * dL;
    const float r32 = __expf(-32.0f * dL);
    const float d32 = 32.0f * dL;

    const float2* pln = g_loc[plane];
    const int seg = warp * 1024;
    float cu = 0.f, cv = 0.f;

    #pragma unroll 2
    for (int ti = -2; ti < 32; ti++) {          // 2 warm-up subtiles (64 chunks)
        int c = seg + ti * 32 + lane;
        float2 l = (c >= 0) ? pln[c] : make_float2(0.f, 0.f);

        float au = l.x, av = l.y;
        #pragma unroll
        for (int kk = 0; kk < 5; kk++) {
            int off = 1 << kk;
            float ou = __shfl_up_sync(0xffffffffu, au, off);
            float ov = __shfl_up_sync(0xffffffffu, av, off);
            if (lane >= off) {
                av = fmaf(rho[kk], fmaf(del[kk], ou, ov), av);
                au = fmaf(rho[kk], ou, au);
            }
        }
        float exu = __shfl_up_sync(0xffffffffu, au, 1);
        float exv = __shfl_up_sync(0xffffffffu, av, 1);
        if (lane == 0) { exu = 0.f; exv = 0.f; }

        if (ti >= 0 && c < NC) {
            float su = fmaf(pl, cu, exu);
            float sv = fmaf(pl, fmaf(dl, cu, cv), exv);
            *(float2*)(g_st + ((size_t)c * SUB + s) * 6 + 2 * b) = make_float2(su, sv);
        }
        float iu = __shfl_sync(0xffffffffu, au, 31);
        float iv = __shfl_sync(0xffffffffu, av, 31);
        cv = fmaf(r32, fmaf(d32, cu, cv), iv);
        cu = fmaf(r32, cu, iu);
    }
}

// ---------------------------------------------------------------------------
// k2c: main pass (R6 config — best measured). thread = (chunk, s), 25 steps,
// init from scanned states, counts staged in smem via int4, single bf16 load.
// Block = 4 chunks x 64 s = 256 threads.
// ---------------------------------------------------------------------------
__global__ __launch_bounds__(256) void k2c_main(
    const float* __restrict__ Vo, const float* __restrict__ W,
    const float* __restrict__ Ksp, const float* __restrict__ tausp,
    float* __restrict__ out, int T, int NC)
{
    __shared__ __align__(16) uint8_t scnt[K2ROWS * SUB];   // 19.2KB

    const int tid = threadIdx.x;
    const long tbt = (long)blockIdx.x * (K2CH * LCH);

    // stage count rows [tbt-200, tbt+100) as int4 (coalesced, zero-pad)
    #pragma unroll
    for (int idx = tid; idx < K2ROWS * SUB / 16; idx += 256) {
        long g = tbt - THIST + (idx >> 2);
        int4 v = make_int4(0, 0, 0, 0);
        if (g >= 0 && g < TCAP)
            v = ((const int4*)(g_zc + g * SUB))[idx & 3];
        ((int4*)scnt)[idx] = v;
    }
    __syncthreads();

    const int cl = tid >> 6, s = tid & 63;
    const int c = blockIdx.x * K2CH + cl;
    if (c >= NC) return;
    const long t0 = (long)c * LCH;
    const int steps = (T - t0 < (long)LCH) ? (int)(T - t0) : LCH;

    float inv0 = 1.0f / expf(tausp[0]);
    float inv1 = 1.0f / expf(tausp[1]);
    float inv2 = 1.0f / expf(tausp[2]);
    float r0 = __expf(-inv0), r1 = __expf(-inv1), r2 = __expf(-inv2);
    float e0 = __expf(-(float)THIST * inv0);
    float e1 = __expf(-(float)THIST * inv1);
    float e2 = __expf(-(float)THIST * inv2);
    float K0 = Ksp[s * 3 + 0], K1 = Ksp[s * 3 + 1], K2 = Ksp[s * 3 + 2];

    const float* pc = g_st + ((size_t)c * SUB + s) * 6;
    float2 a0 = *(const float2*)(pc + 0);
    float2 a1 = *(const float2*)(pc + 2);
    float2 a2 = *(const float2*)(pc + 4);
    float u0c = a0.x, v0c = a0.y, u1c = a1.x, v1c = a1.y, u2c = a2.x, v2c = a2.y;
    float u0o = 0.f, v0o = 0.f, u1o = 0.f, v1o = 0.f, u2o = 0.f, v2o = 0.f;
    if (c >= OLDC) {
        const float* po = g_st + ((size_t)(c - OLDC) * SUB + s) * 6;
        float2 b0 = *(const float2*)(po + 0);
        float2 b1 = *(const float2*)(po + 2);
        float2 b2 = *(const float2*)(po + 4);
        u0o = b0.x; v0o = b0.y; u1o = b1.x; v1o = b1.y; u2o = b2.x; v2o = b2.y;
    }

    const float vo = Vo[0];
    const float ws = W[s];
    const __nv_bfloat16* Bp = g_B + (size_t)t0 * SUB + s;
    float* op = out + (size_t)t0 * SUB + s;
    const uint8_t* cnew = scnt + (cl * LCH + THIST) * SUB + s;
    const uint8_t* cold = scnt + (cl * LCH) * SUB + s;

    if (e0 < 1e-8f && e1 < 1e-8f) {
        // Light path: only basis-2 truncation correction is numerically live.
        const float Kq2 = K2 * e2 * (float)THIST * inv2;
        const float Ke2 = K2 * e2;
        #pragma unroll 5
        for (int i = 0; i < steps; i++) {
            float filt = fmaf(K0, v0c, fmaf(K1, v1c, K2 * v2c));
            filt = fmaf(-Kq2, u2o, filt);
            filt = fmaf(-Ke2, v2o, filt);

            float x = __bfloat162float(Bp[(size_t)i * SUB]) + filt;
            float sg = __fdividef(1.0f, 1.0f + __expf(-x));
            op[(size_t)i * SUB] = fmaf(ws, sg, vo);

            float zn = (float)(int)cnew[i * SUB];
            float zo = (float)(int)cold[i * SUB];
            v0c = r0 * fmaf(u0c, inv0, v0c);  u0c = fmaf(r0, u0c, zn);
            v1c = r1 * fmaf(u1c, inv1, v1c);  u1c = fmaf(r1, u1c, zn);
            v2c = r2 * fmaf(u2c, inv2, v2c);  u2c = fmaf(r2, u2c, zn);
            v2o = r2 * fmaf(u2o, inv2, v2o);  u2o = fmaf(r2, u2o, zo);
        }
    } else {
        // Full path (generic taus)
        float q0 = e0 * (float)THIST * inv0;
        float q1 = e1 * (float)THIST * inv1;
        float q2 = e2 * (float)THIST * inv2;
        #pragma unroll 5
        for (int i = 0; i < steps; i++) {
            float tr0 = fmaf(-q0, u0o, v0c); tr0 = fmaf(-e0, v0o, tr0);
            float tr1 = fmaf(-q1, u1o, v1c); tr1 = fmaf(-e1, v1o, tr1);
            float tr2 = fmaf(-q2, u2o, v2c); tr2 = fmaf(-e2, v2o, tr2);
            float filt = fmaf(K0, tr0, fmaf(K1, tr1, K2 * tr2));

            float x = __bfloat162float(Bp[(size_t)i * SUB]) + filt;
            float sg = __fdividef(1.0f, 1.0f + __expf(-x));
            op[(size_t)i * SUB] = fmaf(ws, sg, vo);

            float zn = (float)(int)cnew[i * SUB];
            float zo = (float)(int)cold[i * SUB];
            v0c = r0 * fmaf(u0c, inv0, v0c);  u0c = fmaf(r0, u0c, zn);
            v0o = r0 * fmaf(u0o, inv0, v0o);  u0o = fmaf(r0, u0o, zo);
            v1c = r1 * fmaf(u1c, inv1, v1c);  u1c = fmaf(r1, u1c, zn);
            v1o = r1 * fmaf(u1o, inv1, v1o);  u1o = fmaf(r1, u1o, zo);
            v2c = r2 * fmaf(u2c, inv2, v2c);  u2c = fmaf(r2, u2c, zn);
            v2o = r2 * fmaf(u2o, inv2, v2o);  u2o = fmaf(r2, u2o, zo);
        }
    }
}

// ---------------------------------------------------------------------------
extern "C" void kernel_launch(void* const* d_in, const int* in_sizes, int n_in,
                              void* d_out, int out_size)
{
    const float* S     = (const float*)d_in[0];
    const float* Y     = (const float*)d_in[1];
    const float* Z     = (const float*)d_in[2];
    const float* C     = (const float*)d_in[3];
    const float* Vo    = (const float*)d_in[4];
    const float* W     = (const float*)d_in[5];
    const float* theta = (const float*)d_in[6];
    const float* Ksp   = (const float*)d_in[7];
    const float* tausp = (const float*)d_in[8];
    float* out = (float*)d_out;

    int T = in_sizes[0] / SUB;
    if (T > TCAP) T = TCAP;
    const int NC = (T + LCH - 1) / LCH;

    const int gA = (T + 99) / 100;
    const int gB = (T + 63) / 64;
    kA_combined<<<gA + gB, 256>>>(S, Y, Z, C, theta, tausp, T, NC, gA);

    k2b_scan<<<3 * SUB, 128>>>(tausp, NC);

    const int gC = (NC + K2CH - 1) / K2CH;
    k2c_main<<<gC, 256>>>(Vo, W, Ksp, tausp, out, T, NC);
}

// round 13
// speedup vs baseline: 1.2132x; 1.0027x over previous
#include <cuda_runtime.h>
#include <cuda_bf16.h>
#include <stdint.h>

// Fixed dataset: SUB_NO=64, T_HIST=200, T_DATA=100000, delta_spike=0
#define SUB    64
#define THIST  200
#define LCH    25                 // chunk length; divides THIST
#define OLDC   (THIST / LCH)      // 8 chunks back = t-200
#define NCPAD  4096               // padded chunk capacity (4 warp segments of 1024)
#define TCAP   (NCPAD * LCH)      // 102400
#define K2CH   4                  // chunks per k2c block (100 t rows)
#define K2ROWS (K2CH * LCH + THIST)   // 300 count rows staged

// Device scratch (zero-initialized at module load; never freed)
__device__ __align__(16) uint8_t g_zc[(size_t)TCAP * SUB];   // spike counts Zc[t][s]
__device__ __nv_bfloat16   g_B[(size_t)TCAP * SUB];          // S + theta + Y@C^T (bf16)
__device__ float2          g_loc[3 * SUB][NCPAD];            // [b*64+s][c] local (Lu,Lv)
__device__ float           g_st[(size_t)NCPAD * SUB * 6];    // [c][s][b*2] exclusive (u,v)

// ---------------------------------------------------------------------------
// kA (block-specialized): blocks [0,gA) run branch A (spike side), blocks
// [gA, gA+gB) run branch B (B-matrix side). Disjoint inputs, overlapped SMs.
// smem capped at 25.6KB + 42 regs -> 6 blocks/SM (75% occ target).
// ---------------------------------------------------------------------------
__global__ void __launch_bounds__(256, 6) kA_combined(
    const float* __restrict__ S, const float* __restrict__ Y,
    const float* __restrict__ Z, const float* __restrict__ C,
    const float* __restrict__ theta, const float* __restrict__ tausp,
    int T, int NC, int gA)
{
    __shared__ __align__(16) char smbuf[25600];

    const int tid = threadIdx.x, lane = tid & 31, warp = tid >> 5;

    if ((int)blockIdx.x < gA) {
        // ================= Branch A: spike side =================
        uint64_t* msh   = (uint64_t*)(smbuf);                // 104*8 = 832
        uint64_t* CmA   = (uint64_t*)(smbuf + 832);          // 64*8 = 512
        float2  (*shloc)[4] = (float2(*)[4])(smbuf + 1344);  // 192*4*8 = 6144
        float*   s_cst  = (float*)(smbuf + 7488);            // 9 floats

        const long tb = (long)blockIdx.x * 100;

        // permuted C masks via float2 ballots (warp sweeps one C row)
        #pragma unroll
        for (int ss = 0; ss < 8; ss++) {
            int s = warp * 8 + ss;
            float2 cv = ((const float2*)(C + s * SUB))[lane];
            unsigned m0 = __ballot_sync(0xffffffffu, cv.x != 0.f);  // subunits 2k
            unsigned m1 = __ballot_sync(0xffffffffu, cv.y != 0.f);  // subunits 2k+1
            if (lane == 0) CmA[s] = (uint64_t)m0 | ((uint64_t)m1 << 32);
        }
        // pack Z rows (permuted bit order matching CmA)
        #pragma unroll
        for (int rr = 0; rr < 13; rr++) {
            int t = warp * 13 + rr;
            long gt = tb + t;
            bool valid = (t < 100) && (gt < T);
            float2 z = make_float2(0.f, 0.f);
            if (valid) z = ((const float2*)(Z + gt * SUB))[lane];
            unsigned m0 = __ballot_sync(0xffffffffu, z.x != 0.f);
            unsigned m1 = __ballot_sync(0xffffffffu, z.y != 0.f);
            if (lane == 0 && t < 100)
                msh[t] = (uint64_t)m0 | ((uint64_t)m1 << 32);
        }
        if (tid < 3) {
            float inv = 1.0f / expf(tausp[tid]);
            float r   = __expf(-inv);
            s_cst[tid]     = inv;
            s_cst[3 + tid] = r;
            s_cst[6 + tid] = r * inv;      // chain-break constant
        }
        __syncthreads();

        // locals + direct count stores: thread = (chunk-in-block, s)
        {
            const int cl = tid >> 6, s = tid & 63;
            const uint64_t cm = CmA[s];
            const float r0 = s_cst[3], r1 = s_cst[4], r2 = s_cst[5];
            const float ri0 = s_cst[6], ri1 = s_cst[7], ri2 = s_cst[8];

            float w0 = 1.f, w1 = 1.f, w2 = 1.f;
            float y0 = 0.f, y1 = 0.f, y2 = 0.f;
            float lu0=0.f,lu1=0.f,lu2=0.f, lv0=0.f,lv1=0.f,lv2=0.f;
            const int rbase = cl * LCH + (LCH - 1);
            uint8_t* zcp = g_zc + (tb + rbase) * SUB + s;
            #pragma unroll
            for (int j = 0; j < LCH; j++) {
                int row = rbase - j;
                int cnti = __popcll(msh[row] & cm);
                zcp[-(long)j * SUB] = (uint8_t)cnti;   // coalesced STG.U8
                float cnt = (float)cnti;
                lu0 = fmaf(w0, cnt, lu0);  lv0 = fmaf(y0, cnt, lv0);
                lu1 = fmaf(w1, cnt, lu1);  lv1 = fmaf(y1, cnt, lv1);
                lu2 = fmaf(w2, cnt, lu2);  lv2 = fmaf(y2, cnt, lv2);
                y0 = fmaf(r0, y0, ri0 * w0);  w0 *= r0;   // 1-FMA y-chain
                y1 = fmaf(r1, y1, ri1 * w1);  w1 *= r1;
                y2 = fmaf(r2, y2, ri2 * w2);  w2 *= r2;
            }
            shloc[s][cl]           = make_float2(lu0, lv0);
            shloc[SUB + s][cl]     = make_float2(lu1, lv1);
            shloc[2 * SUB + s][cl] = make_float2(lu2, lv2);
        }
        __syncthreads();

        if (tid < 3 * SUB) {
            #pragma unroll
            for (int k = 0; k < 4; k++) {
                int cc = blockIdx.x * 4 + k;
                if (cc < NC) g_loc[tid][cc] = shloc[tid][k];
            }
        }
    } else {
        // ================= Branch B: B-matrix side =================
        float*          Ysh = (float*)(smbuf);               // 64*65*4 = 16640
        __nv_bfloat16*  Xsh = (__nv_bfloat16*)(smbuf + 16640); // 64*66*2 = 8448
        uint64_t*       CmB = (uint64_t*)(smbuf + 25088);    // 512

        const long tb = (long)(blockIdx.x - gA) * 64;

        // unpermuted C masks via scalar ballots
        #pragma unroll
        for (int ss = 0; ss < 8; ss++) {
            int s = warp * 8 + ss;
            float c0 = C[s * SUB + lane];
            float c1 = C[s * SUB + 32 + lane];
            unsigned m0 = __ballot_sync(0xffffffffu, c0 != 0.f);
            unsigned m1 = __ballot_sync(0xffffffffu, c1 != 0.f);
            if (lane == 0) CmB[s] = (uint64_t)m0 | ((uint64_t)m1 << 32);
        }
        // stage Y tile (coalesced)
        #pragma unroll
        for (int idx = tid; idx < 64 * SUB; idx += 256) {
            int t = idx >> 6;
            long gt = tb + t;
            Ysh[t * 65 + (idx & 63)] = (gt < T) ? Y[tb * SUB + idx] : 0.f;
        }
        __syncthreads();

        // bit-gather raw+theta: warp per s, lanes sweep t (2 halves of 64)
        #pragma unroll
        for (int uu = 0; uu < 8; uu++) {
            int s = uu * 8 + warp;
            uint64_t m0 = CmB[s];
            float th = __ldg(theta + s);
            #pragma unroll
            for (int half = 0; half < 2; half++) {
                int t = half * 32 + lane;
                float acc = th;
                uint64_t m = m0;
                while (m) {
                    int j = __ffsll((long long)m) - 1;
                    m &= m - 1;
                    acc += Ysh[t * 65 + j];
                }
                Xsh[t * 66 + s] = __float2bfloat16(acc);
            }
        }
        __syncthreads();

        // B = raw + theta + S, bf16, coalesced
        #pragma unroll
        for (int idx = tid; idx < 64 * SUB; idx += 256) {
            int t = idx >> 6, s = idx & 63;
            long gt = tb + t;
            if (gt < T) {
                float x = __bfloat162float(Xsh[t * 66 + s]) + S[tb * SUB + idx];
                g_B[tb * SUB + idx] = __float2bfloat16(x);
            }
        }
    }
}

// ---------------------------------------------------------------------------
// k2b: windowed scan — decay over 64 chunks < 1e-19; each warp scans its
// 1024-chunk segment independently after a 2-subtile warm-up.
// ---------------------------------------------------------------------------
__global__ __launch_bounds__(128) void k2b_scan(const float* __restrict__ tausp, int NC)
{
    const int plane = blockIdx.x;               // 0..191
    const int b = plane >> 6, s = plane & 63;
    const int warp = threadIdx.x >> 5, lane = threadIdx.x & 31;

    const float inv = 1.0f / expf(tausp[b]);
    const float dL  = (float)LCH * inv;
    float rho[5], del[5];
    #pragma unroll
    for (int k = 0; k < 5; k++) {
        float off = (float)(1 << k);
        rho[k] = __expf(-off * dL);
        del[k] = off * dL;
    }
    const float pl  = __expf(-(float)lane * dL);
    const float dl  = (float)lane * dL;
    const float r32 = __expf(-32.0f * dL);
    const float rd32 = r32 * 32.0f * dL;        // chain-break constant

    const float2* pln = g_loc[plane];
    const int seg = warp * 1024;
    float cu = 0.f, cv = 0.f;

    #pragma unroll 2
    for (int ti = -2; ti < 32; ti++) {          // 2 warm-up subtiles (64 chunks)
        int c = seg + ti * 32 + lane;
        float2 l = (c >= 0) ? pln[c] : make_float2(0.f, 0.f);

        float au = l.x, av = l.y;
        #pragma unroll
        for (int kk = 0; kk < 5; kk++) {
            int off = 1 << kk;
            float ou = __shfl_up_sync(0xffffffffu, au, off);
            float ov = __shfl_up_sync(0xffffffffu, av, off);
            if (lane >= off) {
                av = fmaf(rho[kk], fmaf(del[kk], ou, ov), av);
                au = fmaf(rho[kk], ou, au);
            }
        }
        float exu = __shfl_up_sync(0xffffffffu, au, 1);
        float exv = __shfl_up_sync(0xffffffffu, av, 1);
        if (lane == 0) { exu = 0.f; exv = 0.f; }

        if (ti >= 0 && c < NC) {
            float su = fmaf(pl, cu, exu);
            float sv = fmaf(pl, fmaf(dl, cu, cv), exv);
            *(float2*)(g_st + ((size_t)c * SUB + s) * 6 + 2 * b) = make_float2(su, sv);
        }
        float iu = __shfl_sync(0xffffffffu, au, 31);
        float iv = __shfl_sync(0xffffffffu, av, 31);
        cv = fmaf(r32, cv, fmaf(rd32, cu, iv));  // 1-FMA cv-chain
        cu = fmaf(r32, cu, iu);
    }
}

// ---------------------------------------------------------------------------
// k2c: main pass (R6 staging config + broken recurrence chains).
// thread = (chunk, s), 25 steps; v-chain is now 1 FMA/step.
// ---------------------------------------------------------------------------
__global__ __launch_bounds__(256) void k2c_main(
    const float* __restrict__ Vo, const float* __restrict__ W,
    const float* __restrict__ Ksp, const float* __restrict__ tausp,
    float* __restrict__ out, int T, int NC)
{
    __shared__ __align__(16) uint8_t scnt[K2ROWS * SUB];   // 19.2KB

    const int tid = threadIdx.x;
    const long tbt = (long)blockIdx.x * (K2CH * LCH);

    // stage count rows [tbt-200, tbt+100) as int4 (coalesced, zero-pad)
    #pragma unroll
    for (int idx = tid; idx < K2ROWS * SUB / 16; idx += 256) {
        long g = tbt - THIST + (idx >> 2);
        int4 v = make_int4(0, 0, 0, 0);
        if (g >= 0 && g < TCAP)
            v = ((const int4*)(g_zc + g * SUB))[idx & 3];
        ((int4*)scnt)[idx] = v;
    }
    __syncthreads();

    const int cl = tid >> 6, s = tid & 63;
    const int c = blockIdx.x * K2CH + cl;
    if (c >= NC) return;
    const long t0 = (long)c * LCH;
    const int steps = (T - t0 < (long)LCH) ? (int)(T - t0) : LCH;

    float inv0 = 1.0f / expf(tausp[0]);
    float inv1 = 1.0f / expf(tausp[1]);
    float inv2 = 1.0f / expf(tausp[2]);
    float r0 = __expf(-inv0), r1 = __expf(-inv1), r2 = __expf(-inv2);
    float ri0 = r0 * inv0, ri1 = r1 * inv1, ri2 = r2 * inv2;
    float e0 = __expf(-(float)THIST * inv0);
    float e1 = __expf(-(float)THIST * inv1);
    float e2 = __expf(-(float)THIST * inv2);
    float K0 = Ksp[s * 3 + 0], K1 = Ksp[s * 3 + 1], K2 = Ksp[s * 3 + 2];

    const float* pc = g_st + ((size_t)c * SUB + s) * 6;
    float2 a0 = *(const float2*)(pc + 0);
    float2 a1 = *(const float2*)(pc + 2);
    float2 a2 = *(const float2*)(pc + 4);
    float u0c = a0.x, v0c = a0.y, u1c = a1.x, v1c = a1.y, u2c = a2.x, v2c = a2.y;
    float u0o = 0.f, v0o = 0.f, u1o = 0.f, v1o = 0.f, u2o = 0.f, v2o = 0.f;
    if (c >= OLDC) {
        const float* po = g_st + ((size_t)(c - OLDC) * SUB + s) * 6;
        float2 b0 = *(const float2*)(po + 0);
        float2 b1 = *(const float2*)(po + 2);
        float2 b2 = *(const float2*)(po + 4);
        u0o = b0.x; v0o = b0.y; u1o = b1.x; v1o = b1.y; u2o = b2.x; v2o = b2.y;
    }

    const float vo = Vo[0];
    const float ws = W[s];
    const __nv_bfloat16* Bp = g_B + (size_t)t0 * SUB + s;
    float* op = out + (size_t)t0 * SUB + s;
    const uint8_t* cnew = scnt + (cl * LCH + THIST) * SUB + s;
    const uint8_t* cold = scnt + (cl * LCH) * SUB + s;

    if (e0 < 1e-8f && e1 < 1e-8f) {
        // Light path: only basis-2 truncation correction is numerically live.
        const float Kq2 = K2 * e2 * (float)THIST * inv2;
        const float Ke2 = K2 * e2;
        #pragma unroll 5
        for (int i = 0; i < steps; i++) {
            float filt = fmaf(K0, v0c, fmaf(K1, v1c, K2 * v2c));
            filt = fmaf(-Kq2, u2o, filt);
            filt = fmaf(-Ke2, v2o, filt);

            float x = __bfloat162float(Bp[(size_t)i * SUB]) + filt;
            float sg = __fdividef(1.0f, 1.0f + __expf(-x));
            op[(size_t)i * SUB] = fmaf(ws, sg, vo);

            float zn = (float)(int)cnew[i * SUB];
            float zo = (float)(int)cold[i * SUB];
            v0c = fmaf(r0, v0c, ri0 * u0c);  u0c = fmaf(r0, u0c, zn);
            v1c = fmaf(r1, v1c, ri1 * u1c);  u1c = fmaf(r1, u1c, zn);
            v2c = fmaf(r2, v2c, ri2 * u2c);  u2c = fmaf(r2, u2c, zn);
            v2o = fmaf(r2, v2o, ri2 * u2o);  u2o = fmaf(r2, u2o, zo);
        }
    } else {
        // Full path (generic taus)
        float q0 = e0 * (float)THIST * inv0;
        float q1 = e1 * (float)THIST * inv1;
        float q2 = e2 * (float)THIST * inv2;
        #pragma unroll 5
        for (int i = 0; i < steps; i++) {
            float tr0 = fmaf(-q0, u0o, v0c); tr0 = fmaf(-e0, v0o, tr0);
            float tr1 = fmaf(-q1, u1o, v1c); tr1 = fmaf(-e1, v1o, tr1);
            float tr2 = fmaf(-q2, u2o, v2c); tr2 = fmaf(-e2, v2o, tr2);
            float filt = fmaf(K0, tr0, fmaf(K1, tr1, K2 * tr2));

            float x = __bfloat162float(Bp[(size_t)i * SUB]) + filt;
            float sg = __fdividef(1.0f, 1.0f + __expf(-x));
            op[(size_t)i * SUB] = fmaf(ws, sg, vo);

            float zn = (float)(int)cnew[i * SUB];
            float zo = (float)(int)cold[i * SUB];
            v0c = fmaf(r0, v0c, ri0 * u0c);  u0c = fmaf(r0, u0c, zn);
            v0o = fmaf(r0, v0o, ri0 * u0o);  u0o = fmaf(r0, u0o, zo);
            v1c = fmaf(r1, v1c, ri1 * u1c);  u1c = fmaf(r1, u1c, zn);
            v1o = fmaf(r1, v1o, ri1 * u1o);  u1o = fmaf(r1, u1o, zo);
            v2c = fmaf(r2, v2c, ri2 * u2c);  u2c = fmaf(r2, u2c, zn);
            v2o = fmaf(r2, v2o, ri2 * u2o);  u2o = fmaf(r2, u2o, zo);
        }
    }
}

// ---------------------------------------------------------------------------
extern "C" void kernel_launch(void* const* d_in, const int* in_sizes, int n_in,
                              void* d_out, int out_size)
{
    const float* S     = (const float*)d_in[0];
    const float* Y     = (const float*)d_in[1];
    const float* Z     = (const float*)d_in[2];
    const float* C     = (const float*)d_in[3];
    const float* Vo    = (const float*)d_in[4];
    const float* W     = (const float*)d_in[5];
    const float* theta = (const float*)d_in[6];
    const float* Ksp   = (const float*)d_in[7];
    const float* tausp = (const float*)d_in[8];
    float* out = (float*)d_out;

    int T = in_sizes[0] / SUB;
    if (T > TCAP) T = TCAP;
    const int NC = (T + LCH - 1) / LCH;

    const int gA = (T + 99) / 100;
    const int gB = (T + 63) / 64;
    kA_combined<<<gA + gB, 256>>>(S, Y, Z, C, theta, tausp, T, NC, gA);

    k2b_scan<<<3 * SUB, 128>>>(tausp, NC);

    const int gC = (NC + K2CH - 1) / K2CH;
    k2c_main<<<gC, 256>>>(Vo, W, Ksp, tausp, out, T, NC);
}

// round 14
// speedup vs baseline: 1.3492x; 1.1121x over previous
#include <cuda_runtime.h>
#include <cuda_bf16.h>
#include <stdint.h>

// Fixed dataset: SUB_NO=64, T_HIST=200, T_DATA=100000, delta_spike=0
#define SUB    64
#define THIST  200
#define LCH    25                 // chunk length; divides THIST
#define OLDC   (THIST / LCH)      // 8 chunks back = t-200
#define NCPAD  4096               // padded chunk capacity (4 warp segments of 1024)
#define TCAP   (NCPAD * LCH)      // 102400
#define K2CH   4                  // chunks per k2c block (100 t rows)
#define K2ROWS (K2CH * LCH + THIST)   // 300 count rows staged

// Device scratch (zero-initialized at module load; never freed)
__device__ __align__(16) uint8_t g_zc[(size_t)TCAP * SUB];   // spike counts Zc[t][s]
__device__ __nv_bfloat16   g_B[(size_t)TCAP * SUB];          // S + theta + Y@C^T (bf16)
__device__ float2          g_loc[3 * SUB][NCPAD];            // [b*64+s][c] local (Lu,Lv)
__device__ float           g_st[(size_t)NCPAD * SUB * 6];    // [c][s][b*2] exclusive (u,v)

// ---------------------------------------------------------------------------
// kA (block-specialized): blocks [0,gA) run branch A (spike side), blocks
// [gA, gA+gB) run branch B (B-matrix side). Disjoint inputs, overlapped SMs.
// ---------------------------------------------------------------------------
__global__ void __launch_bounds__(256, 6) kA_combined(
    const float* __restrict__ S, const float* __restrict__ Y,
    const float* __restrict__ Z, const float* __restrict__ C,
    const float* __restrict__ theta, const float* __restrict__ tausp,
    int T, int NC, int gA)
{
    __shared__ __align__(16) char smbuf[30720];

    const int tid = threadIdx.x, lane = tid & 31, warp = tid >> 5;

    if ((int)blockIdx.x < gA) {
        // ================= Branch A: spike side =================
        uint64_t* msh   = (uint64_t*)(smbuf);                // 104*8 = 832
        uint64_t* CmA   = (uint64_t*)(smbuf + 832);          // 64*8 = 512
        float2  (*shloc)[4] = (float2(*)[4])(smbuf + 1344);  // 192*4*8 = 6144
        float*   s_cst  = (float*)(smbuf + 7488);            // 9 floats

        const long tb = (long)blockIdx.x * 100;

        // permuted C masks via float2 ballots (warp sweeps one C row)
        #pragma unroll
        for (int ss = 0; ss < 8; ss++) {
            int s = warp * 8 + ss;
            float2 cv = ((const float2*)(C + s * SUB))[lane];
            unsigned m0 = __ballot_sync(0xffffffffu, cv.x != 0.f);  // subunits 2k
            unsigned m1 = __ballot_sync(0xffffffffu, cv.y != 0.f);  // subunits 2k+1
            if (lane == 0) CmA[s] = (uint64_t)m0 | ((uint64_t)m1 << 32);
        }
        // pack Z rows (permuted bit order matching CmA)
        #pragma unroll
        for (int rr = 0; rr < 13; rr++) {
            int t = warp * 13 + rr;
            long gt = tb + t;
            bool valid = (t < 100) && (gt < T);
            float2 z = make_float2(0.f, 0.f);
            if (valid) z = ((const float2*)(Z + gt * SUB))[lane];
            unsigned m0 = __ballot_sync(0xffffffffu, z.x != 0.f);
            unsigned m1 = __ballot_sync(0xffffffffu, z.y != 0.f);
            if (lane == 0 && t < 100)
                msh[t] = (uint64_t)m0 | ((uint64_t)m1 << 32);
        }
        if (tid < 3) {
            float inv = 1.0f / expf(tausp[tid]);
            float r   = __expf(-inv);
            s_cst[tid]     = inv;
            s_cst[3 + tid] = r;
            s_cst[6 + tid] = r * inv;      // chain-break constant
        }
        __syncthreads();

        // locals + direct count stores: thread = (chunk-in-block, s)
        {
            const int cl = tid >> 6, s = tid & 63;
            const uint64_t cm = CmA[s];
            const float r0 = s_cst[3], r1 = s_cst[4], r2 = s_cst[5];
            const float ri0 = s_cst[6], ri1 = s_cst[7], ri2 = s_cst[8];

            float w0 = 1.f, w1 = 1.f, w2 = 1.f;
            float y0 = 0.f, y1 = 0.f, y2 = 0.f;
            float lu0=0.f,lu1=0.f,lu2=0.f, lv0=0.f,lv1=0.f,lv2=0.f;
            const int rbase = cl * LCH + (LCH - 1);
            uint8_t* zcp = g_zc + (tb + rbase) * SUB + s;
            #pragma unroll
            for (int j = 0; j < LCH; j++) {
                int row = rbase - j;
                int cnti = __popcll(msh[row] & cm);
                zcp[-(long)j * SUB] = (uint8_t)cnti;   // coalesced STG.U8
                float cnt = (float)cnti;
                lu0 = fmaf(w0, cnt, lu0);  lv0 = fmaf(y0, cnt, lv0);
                lu1 = fmaf(w1, cnt, lu1);  lv1 = fmaf(y1, cnt, lv1);
                lu2 = fmaf(w2, cnt, lu2);  lv2 = fmaf(y2, cnt, lv2);
                y0 = fmaf(r0, y0, ri0 * w0);  w0 *= r0;   // 1-FMA y-chain
                y1 = fmaf(r1, y1, ri1 * w1);  w1 *= r1;
                y2 = fmaf(r2, y2, ri2 * w2);  w2 *= r2;
            }
            shloc[s][cl]           = make_float2(lu0, lv0);
            shloc[SUB + s][cl]     = make_float2(lu1, lv1);
            shloc[2 * SUB + s][cl] = make_float2(lu2, lv2);
        }
        __syncthreads();

        if (tid < 3 * SUB) {
            #pragma unroll
            for (int k = 0; k < 4; k++) {
                int cc = blockIdx.x * 4 + k;
                if (cc < NC) g_loc[tid][cc] = shloc[tid][k];
            }
        }
    } else {
        // ================= Branch B: B-matrix side =================
        float*          Ysh  = (float*)(smbuf);                  // 64*65*4 = 16640
        __nv_bfloat16*  Xsh  = (__nv_bfloat16*)(smbuf + 16640);  // 64*66*2 = 8448
        uint64_t*       CmB  = (uint64_t*)(smbuf + 25088);       // 512
        uint8_t*        idxs = (uint8_t*)(smbuf + 25600);        // 64*68 = 4352
        int*            cnt4 = (int*)(smbuf + 29952);            // 256

        const long tb = (long)(blockIdx.x - gA) * 64;

        // unpermuted C masks via scalar ballots
        #pragma unroll
        for (int ss = 0; ss < 8; ss++) {
            int s = warp * 8 + ss;
            float c0 = C[s * SUB + lane];
            float c1 = C[s * SUB + 32 + lane];
            unsigned m0 = __ballot_sync(0xffffffffu, c0 != 0.f);
            unsigned m1 = __ballot_sync(0xffffffffu, c1 != 0.f);
            if (lane == 0) CmB[s] = (uint64_t)m0 | ((uint64_t)m1 << 32);
        }
        // stage Y tile (coalesced) + zero the dummy column 64
        #pragma unroll
        for (int idx = tid; idx < 64 * SUB; idx += 256) {
            int t = idx >> 6;
            long gt = tb + t;
            Ysh[t * 65 + (idx & 63)] = (gt < T) ? Y[tb * SUB + idx] : 0.f;
        }
        if (tid < 64) Ysh[tid * 65 + 64] = 0.f;
        __syncthreads();

        // Build per-s index lists (once per block), padded to quads with 64.
        if (tid < SUB) {
            uint64_t m = CmB[tid];
            uint8_t* ip = idxs + tid * 68;
            int k = 0;
            while (m) {
                ip[k++] = (uint8_t)(__ffsll((long long)m) - 1);
                m &= m - 1;
            }
            while (k & 3) ip[k++] = 64;    // dummy -> zero column
            cnt4[tid] = k;
        }
        __syncthreads();

        // Quad-index gather: warp per s, lanes = t, BOTH halves per index.
        #pragma unroll
        for (int uu = 0; uu < 8; uu++) {
            int s = uu * 8 + warp;
            float th = __ldg(theta + s);
            float acc0 = th, acc1 = th;
            const uint8_t* ip = idxs + s * 68;
            const int n4 = cnt4[s];
            const int base0 = lane * 65;
            const int base1 = (lane + 32) * 65;
            for (int k = 0; k < n4; k += 4) {
                uchar4 j4 = *(const uchar4*)(ip + k);   // broadcast LDS.U32
                acc0 += Ysh[base0 + j4.x];  acc1 += Ysh[base1 + j4.x];
                acc0 += Ysh[base0 + j4.y];  acc1 += Ysh[base1 + j4.y];
                acc0 += Ysh[base0 + j4.z];  acc1 += Ysh[base1 + j4.z];
                acc0 += Ysh[base0 + j4.w];  acc1 += Ysh[base1 + j4.w];
            }
            Xsh[lane * 66 + s]        = __float2bfloat16(acc0);
            Xsh[(lane + 32) * 66 + s] = __float2bfloat16(acc1);
        }
        __syncthreads();

        // B = raw + theta + S, bf16, coalesced
        #pragma unroll
        for (int idx = tid; idx < 64 * SUB; idx += 256) {
            int t = idx >> 6, s = idx & 63;
            long gt = tb + t;
            if (gt < T) {
                float x = __bfloat162float(Xsh[t * 66 + s]) + S[tb * SUB + idx];
                g_B[tb * SUB + idx] = __float2bfloat16(x);
            }
        }
    }
}

// ---------------------------------------------------------------------------
// k2b: windowed scan — decay over 64 chunks < 1e-19; each warp scans its
// 1024-chunk segment independently after a 2-subtile warm-up.
// ---------------------------------------------------------------------------
__global__ __launch_bounds__(128) void k2b_scan(const float* __restrict__ tausp, int NC)
{
    const int plane = blockIdx.x;               // 0..191
    const int b = plane >> 6, s = plane & 63;
    const int warp = threadIdx.x >> 5, lane = threadIdx.x & 31;

    const float inv = 1.0f / expf(tausp[b]);
    const float dL  = (float)LCH * inv;
    float rho[5], del[5];
    #pragma unroll
    for (int k = 0; k < 5; k++) {
        float off = (float)(1 << k);
        rho[k] = __expf(-off * dL);
        del[k] = off * dL;
    }
    const float pl  = __expf(-(float)lane * dL);
    const float dl  = (float)lane * dL;
    const float r32 = __expf(-32.0f * dL);
    const float rd32 = r32 * 32.0f * dL;        // chain-break constant

    const float2* pln = g_loc[plane];
    const int seg = warp * 1024;
    float cu = 0.f, cv = 0.f;

    #pragma unroll 2
    for (int ti = -2; ti < 32; ti++) {          // 2 warm-up subtiles (64 chunks)
        int c = seg + ti * 32 + lane;
        float2 l = (c >= 0) ? pln[c] : make_float2(0.f, 0.f);

        float au = l.x, av = l.y;
        #pragma unroll
        for (int kk = 0; kk < 5; kk++) {
            int off = 1 << kk;
            float ou = __shfl_up_sync(0xffffffffu, au, off);
            float ov = __shfl_up_sync(0xffffffffu, av, off);
            if (lane >= off) {
                av = fmaf(rho[kk], fmaf(del[kk], ou, ov), av);
                au = fmaf(rho[kk], ou, au);
            }
        }
        float exu = __shfl_up_sync(0xffffffffu, au, 1);
        float exv = __shfl_up_sync(0xffffffffu, av, 1);
        if (lane == 0) { exu = 0.f; exv = 0.f; }

        if (ti >= 0 && c < NC) {
            float su = fmaf(pl, cu, exu);
            float sv = fmaf(pl, fmaf(dl, cu, cv), exv);
            *(float2*)(g_st + ((size_t)c * SUB + s) * 6 + 2 * b) = make_float2(su, sv);
        }
        float iu = __shfl_sync(0xffffffffu, au, 31);
        float iv = __shfl_sync(0xffffffffu, av, 31);
        cv = fmaf(r32, cv, fmaf(rd32, cu, iv));  // 1-FMA cv-chain
        cu = fmaf(r32, cu, iu);
    }
}

// ---------------------------------------------------------------------------
// k2c: main pass (best-measured staging config + broken chains).
// thread = (chunk, s), 25 steps; v-chain 1 FMA/step.
// ---------------------------------------------------------------------------
__global__ __launch_bounds__(256) void k2c_main(
    const float* __restrict__ Vo, const float* __restrict__ W,
    const float* __restrict__ Ksp, const float* __restrict__ tausp,
    float* __restrict__ out, int T, int NC)
{
    __shared__ __align__(16) uint8_t scnt[K2ROWS * SUB];   // 19.2KB

    const int tid = threadIdx.x;
    const long tbt = (long)blockIdx.x * (K2CH * LCH);

    // stage count rows [tbt-200, tbt+100) as int4 (coalesced, zero-pad)
    #pragma unroll
    for (int idx = tid; idx < K2ROWS * SUB / 16; idx += 256) {
        long g = tbt - THIST + (idx >> 2);
        int4 v = make_int4(0, 0, 0, 0);
        if (g >= 0 && g < TCAP)
            v = ((const int4*)(g_zc + g * SUB))[idx & 3];
        ((int4*)scnt)[idx] = v;
    }
    __syncthreads();

    const int cl = tid >> 6, s = tid & 63;
    const int c = blockIdx.x * K2CH + cl;
    if (c >= NC) return;
    const long t0 = (long)c * LCH;
    const int steps = (T - t0 < (long)LCH) ? (int)(T - t0) : LCH;

    float inv0 = 1.0f / expf(tausp[0]);
    float inv1 = 1.0f / expf(tausp[1]);
    float inv2 = 1.0f / expf(tausp[2]);
    float r0 = __expf(-inv0), r1 = __expf(-inv1), r2 = __expf(-inv2);
    float ri0 = r0 * inv0, ri1 = r1 * inv1, ri2 = r2 * inv2;
    float e0 = __expf(-(float)THIST * inv0);
    float e1 = __expf(-(float)THIST * inv1);
    float e2 = __expf(-(float)THIST * inv2);
    float K0 = Ksp[s * 3 + 0], K1 = Ksp[s * 3 + 1], K2 = Ksp[s * 3 + 2];

    const float* pc = g_st + ((size_t)c * SUB + s) * 6;
    float2 a0 = *(const float2*)(pc + 0);
    float2 a1 = *(const float2*)(pc + 2);
    float2 a2 = *(const float2*)(pc + 4);
    float u0c = a0.x, v0c = a0.y, u1c = a1.x, v1c = a1.y, u2c = a2.x, v2c = a2.y;
    float u0o = 0.f, v0o = 0.f, u1o = 0.f, v1o = 0.f, u2o = 0.f, v2o = 0.f;
    if (c >= OLDC) {
        const float* po = g_st + ((size_t)(c - OLDC) * SUB + s) * 6;
        float2 b0 = *(const float2*)(po + 0);
        float2 b1 = *(const float2*)(po + 2);
        float2 b2 = *(const float2*)(po + 4);
        u0o = b0.x; v0o = b0.y; u1o = b1.x; v1o = b1.y; u2o = b2.x; v2o = b2.y;
    }

    const float vo = Vo[0];
    const float ws = W[s];
    const __nv_bfloat16* Bp = g_B + (size_t)t0 * SUB + s;
    float* op = out + (size_t)t0 * SUB + s;
    const uint8_t* cnew = scnt + (cl * LCH + THIST) * SUB + s;
    const uint8_t* cold = scnt + (cl * LCH) * SUB + s;

    if (e0 < 1e-8f && e1 < 1e-8f) {
        // Light path: only basis-2 truncation correction is numerically live.
        const float Kq2 = K2 * e2 * (float)THIST * inv2;
        const float Ke2 = K2 * e2;
        #pragma unroll 5
        for (int i = 0; i < steps; i++) {
            float filt = fmaf(K0, v0c, fmaf(K1, v1c, K2 * v2c));
            filt = fmaf(-Kq2, u2o, filt);
            filt = fmaf(-Ke2, v2o, filt);

            float x = __bfloat162float(Bp[(size_t)i * SUB]) + filt;
            float sg = __fdividef(1.0f, 1.0f + __expf(-x));
            op[(size_t)i * SUB] = fmaf(ws, sg, vo);

            float zn = (float)(int)cnew[i * SUB];
            float zo = (float)(int)cold[i * SUB];
            v0c = fmaf(r0, v0c, ri0 * u0c);  u0c = fmaf(r0, u0c, zn);
            v1c = fmaf(r1, v1c, ri1 * u1c);  u1c = fmaf(r1, u1c, zn);
            v2c = fmaf(r2, v2c, ri2 * u2c);  u2c = fmaf(r2, u2c, zn);
            v2o = fmaf(r2, v2o, ri2 * u2o);  u2o = fmaf(r2, u2o, zo);
        }
    } else {
        // Full path (generic taus)
        float q0 = e0 * (float)THIST * inv0;
        float q1 = e1 * (float)THIST * inv1;
        float q2 = e2 * (float)THIST * inv2;
        #pragma unroll 5
        for (int i = 0; i < steps; i++) {
            float tr0 = fmaf(-q0, u0o, v0c); tr0 = fmaf(-e0, v0o, tr0);
            float tr1 = fmaf(-q1, u1o, v1c); tr1 = fmaf(-e1, v1o, tr1);
            float tr2 = fmaf(-q2, u2o, v2c); tr2 = fmaf(-e2, v2o, tr2);
            float filt = fmaf(K0, tr0, fmaf(K1, tr1, K2 * tr2));

            float x = __bfloat162float(Bp[(size_t)i * SUB]) + filt;
            float sg = __fdividef(1.0f, 1.0f + __expf(-x));
            op[(size_t)i * SUB] = fmaf(ws, sg, vo);

            float zn = (float)(int)cnew[i * SUB];
            float zo = (float)(int)cold[i * SUB];
            v0c = fmaf(r0, v0c, ri0 * u0c);  u0c = fmaf(r0, u0c, zn);
            v0o = fmaf(r0, v0o, ri0 * u0o);  u0o = fmaf(r0, u0o, zo);
            v1c = fmaf(r1, v1c, ri1 * u1c);  u1c = fmaf(r1, u1c, zn);
            v1o = fmaf(r1, v1o, ri1 * u1o);  u1o = fmaf(r1, u1o, zo);
            v2c = fmaf(r2, v2c, ri2 * u2c);  u2c = fmaf(r2, u2c, zn);
            v2o = fmaf(r2, v2o, ri2 * u2o);  u2o = fmaf(r2, u2o, zo);
        }
    }
}

// ---------------------------------------------------------------------------
extern "C" void kernel_launch(void* const* d_in, const int* in_sizes, int n_in,
                              void* d_out, int out_size)
{
    const float* S     = (const float*)d_in[0];
    const float* Y     = (const float*)d_in[1];
    const float* Z     = (const float*)d_in[2];
    const float* C     = (const float*)d_in[3];
    const float* Vo    = (const float*)d_in[4];
    const float* W     = (const float*)d_in[5];
    const float* theta = (const float*)d_in[6];
    const float* Ksp   = (const float*)d_in[7];
    const float* tausp = (const float*)d_in[8];
    float* out = (float*)d_out;

    int T = in_sizes[0] / SUB;
    if (T > TCAP) T = TCAP;
    const int NC = (T + LCH - 1) / LCH;

    const int gA = (T + 99) / 100;
    const int gB = (T + 63) / 64;
    kA_combined<<<gA + gB, 256>>>(S, Y, Z, C, theta, tausp, T, NC, gA);

    k2b_scan<<<3 * SUB, 128>>>(tausp, NC);

    const int gC = (NC + K2CH - 1) / K2CH;
    k2c_main<<<gC, 256>>>(Vo, W, Ksp, tausp, out, T, NC);
}

// round 15
// speedup vs baseline: 1.4657x; 1.0863x over previous
#include <cuda_runtime.h>
#include <cuda_bf16.h>
#include <stdint.h>

// Fixed dataset: SUB_NO=64, T_HIST=200, T_DATA=100000, delta_spike=0
#define SUB    64
#define THIST  200
#define LCH    25                 // chunk length; divides THIST
#define OLDC   (THIST / LCH)      // 8 chunks back = t-200
#define NCPAD  4096               // padded chunk capacity (4 warp segments of 1024)
#define TCAP   (NCPAD * LCH)      // 102400
#define K2CH   4                  // chunks per k2c block (100 t rows)
#define SROWS  200                // staged count rows: 100 old + 100 new (live only)

// Device scratch (zero-initialized at module load; never freed)
__device__ __align__(16) uint8_t g_zc[(size_t)TCAP * SUB];   // spike counts Zc[t][s]
__device__ __nv_bfloat16   g_B[(size_t)TCAP * SUB];          // S + theta + Y@C^T (bf16)
__device__ float2          g_loc[3 * SUB][NCPAD];            // [b*64+s][c] local (Lu,Lv)
__device__ float           g_st[(size_t)NCPAD * SUB * 6];    // [c][s][b*2] exclusive (u,v)

// ---------------------------------------------------------------------------
// kA (block-specialized): blocks [0,gA) run branch A (spike side), blocks
// [gA, gA+gB) run branch B (B-matrix side). Disjoint inputs, overlapped SMs.
// ---------------------------------------------------------------------------
__global__ void __launch_bounds__(256, 6) kA_combined(
    const float* __restrict__ S, const float* __restrict__ Y,
    const float* __restrict__ Z, const float* __restrict__ C,
    const float* __restrict__ theta, const float* __restrict__ tausp,
    int T, int NC, int gA)
{
    __shared__ __align__(16) char smbuf[30720];

    const int tid = threadIdx.x, lane = tid & 31, warp = tid >> 5;

    if ((int)blockIdx.x < gA) {
        // ================= Branch A: spike side =================
        uint64_t* msh   = (uint64_t*)(smbuf);                // 104*8 = 832
        uint64_t* CmA   = (uint64_t*)(smbuf + 832);          // 64*8 = 512
        float2  (*shloc)[4] = (float2(*)[4])(smbuf + 1344);  // 192*4*8 = 6144
        float*   s_cst  = (float*)(smbuf + 7488);            // 9 floats

        const long tb = (long)blockIdx.x * 100;

        // permuted C masks via float2 ballots (warp sweeps one C row)
        #pragma unroll
        for (int ss = 0; ss < 8; ss++) {
            int s = warp * 8 + ss;
            float2 cv = ((const float2*)(C + s * SUB))[lane];
            unsigned m0 = __ballot_sync(0xffffffffu, cv.x != 0.f);  // subunits 2k
            unsigned m1 = __ballot_sync(0xffffffffu, cv.y != 0.f);  // subunits 2k+1
            if (lane == 0) CmA[s] = (uint64_t)m0 | ((uint64_t)m1 << 32);
        }
        // pack Z rows (permuted bit order matching CmA)
        #pragma unroll
        for (int rr = 0; rr < 13; rr++) {
            int t = warp * 13 + rr;
            long gt = tb + t;
            bool valid = (t < 100) && (gt < T);
            float2 z = make_float2(0.f, 0.f);
            if (valid) z = ((const float2*)(Z + gt * SUB))[lane];
            unsigned m0 = __ballot_sync(0xffffffffu, z.x != 0.f);
            unsigned m1 = __ballot_sync(0xffffffffu, z.y != 0.f);
            if (lane == 0 && t < 100)
                msh[t] = (uint64_t)m0 | ((uint64_t)m1 << 32);
        }
        if (tid < 3) {
            float inv = 1.0f / expf(tausp[tid]);
            float r   = __expf(-inv);
            s_cst[tid]     = inv;
            s_cst[3 + tid] = r;
            s_cst[6 + tid] = r * inv;      // chain-break constant
        }
        __syncthreads();

        // locals + direct count stores: thread = (chunk-in-block, s)
        {
            const int cl = tid >> 6, s = tid & 63;
            const uint64_t cm = CmA[s];
            const float r0 = s_cst[3], r1 = s_cst[4], r2 = s_cst[5];
            const float ri0 = s_cst[6], ri1 = s_cst[7], ri2 = s_cst[8];

            float w0 = 1.f, w1 = 1.f, w2 = 1.f;
            float y0 = 0.f, y1 = 0.f, y2 = 0.f;
            float lu0=0.f,lu1=0.f,lu2=0.f, lv0=0.f,lv1=0.f,lv2=0.f;
            const int rbase = cl * LCH + (LCH - 1);
            uint8_t* zcp = g_zc + (tb + rbase) * SUB + s;
            #pragma unroll
            for (int j = 0; j < LCH; j++) {
                int row = rbase - j;
                int cnti = __popcll(msh[row] & cm);
                zcp[-(long)j * SUB] = (uint8_t)cnti;   // coalesced STG.U8
                float cnt = (float)cnti;
                lu0 = fmaf(w0, cnt, lu0);  lv0 = fmaf(y0, cnt, lv0);
                lu1 = fmaf(w1, cnt, lu1);  lv1 = fmaf(y1, cnt, lv1);
                lu2 = fmaf(w2, cnt, lu2);  lv2 = fmaf(y2, cnt, lv2);
                y0 = fmaf(r0, y0, ri0 * w0);  w0 *= r0;   // 1-FMA y-chain
                y1 = fmaf(r1, y1, ri1 * w1);  w1 *= r1;
                y2 = fmaf(r2, y2, ri2 * w2);  w2 *= r2;
            }
            shloc[s][cl]           = make_float2(lu0, lv0);
            shloc[SUB + s][cl]     = make_float2(lu1, lv1);
            shloc[2 * SUB + s][cl] = make_float2(lu2, lv2);
        }
        __syncthreads();

        if (tid < 3 * SUB) {
            #pragma unroll
            for (int k = 0; k < 4; k++) {
                int cc = blockIdx.x * 4 + k;
                if (cc < NC) g_loc[tid][cc] = shloc[tid][k];
            }
        }
    } else {
        // ================= Branch B: B-matrix side =================
        float*          Ysh  = (float*)(smbuf);                  // 64*65*4 = 16640
        __nv_bfloat16*  Xsh  = (__nv_bfloat16*)(smbuf + 16640);  // 64*68*2 = 8704
        uint64_t*       CmB  = (uint64_t*)(smbuf + 25344);       // 512
        uint8_t*        idxs = (uint8_t*)(smbuf + 25856);        // 64*68 = 4352
        int*            cnt4 = (int*)(smbuf + 30208);            // 256

        const long tb = (long)(blockIdx.x - gA) * 64;

        // unpermuted C masks via scalar ballots
        #pragma unroll
        for (int ss = 0; ss < 8; ss++) {
            int s = warp * 8 + ss;
            float c0 = C[s * SUB + lane];
            float c1 = C[s * SUB + 32 + lane];
            unsigned m0 = __ballot_sync(0xffffffffu, c0 != 0.f);
            unsigned m1 = __ballot_sync(0xffffffffu, c1 != 0.f);
            if (lane == 0) CmB[s] = (uint64_t)m0 | ((uint64_t)m1 << 32);
        }
        // stage Y tile (coalesced) + zero the dummy column 64
        #pragma unroll
        for (int idx = tid; idx < 64 * SUB; idx += 256) {
            int t = idx >> 6;
            long gt = tb + t;
            Ysh[t * 65 + (idx & 63)] = (gt < T) ? Y[tb * SUB + idx] : 0.f;
        }
        if (tid < 64) Ysh[tid * 65 + 64] = 0.f;
        __syncthreads();

        // Build per-s index lists (once per block), padded to quads with 64.
        if (tid < SUB) {
            uint64_t m = CmB[tid];
            uint8_t* ip = idxs + tid * 68;
            int k = 0;
            while (m) {
                ip[k++] = (uint8_t)(__ffsll((long long)m) - 1);
                m &= m - 1;
            }
            while (k & 3) ip[k++] = 64;    // dummy -> zero column
            cnt4[tid] = k;
        }
        __syncthreads();

        // Quad-index gather: warp per s, lanes = t, BOTH halves per index.
        #pragma unroll
        for (int uu = 0; uu < 8; uu++) {
            int s = uu * 8 + warp;
            float th = __ldg(theta + s);
            float acc0 = th, acc1 = th;
            const uint8_t* ip = idxs + s * 68;
            const int n4 = cnt4[s];
            const int base0 = lane * 65;
            const int base1 = (lane + 32) * 65;
            for (int k = 0; k < n4; k += 4) {
                uchar4 j4 = *(const uchar4*)(ip + k);   // broadcast LDS.U32
                acc0 += Ysh[base0 + j4.x];  acc1 += Ysh[base1 + j4.x];
                acc0 += Ysh[base0 + j4.y];  acc1 += Ysh[base1 + j4.y];
                acc0 += Ysh[base0 + j4.z];  acc1 += Ysh[base1 + j4.z];
                acc0 += Ysh[base0 + j4.w];  acc1 += Ysh[base1 + j4.w];
            }
            Xsh[lane * 68 + s]        = __float2bfloat16(acc0);
            Xsh[(lane + 32) * 68 + s] = __float2bfloat16(acc1);
        }
        __syncthreads();

        // B = raw + theta + S, bf16. Vectorized x4 (stride-68 Xsh keeps
        // 8B alignment for all t).
        if (tb + 64 <= T) {
            const float4* Sp4 = (const float4*)(S + tb * SUB);
            uint2* Bp2 = (uint2*)(g_B + tb * SUB);
            #pragma unroll
            for (int e = tid; e < 64 * SUB / 4; e += 256) {
                int t = e >> 4, sg = (e & 15) * 4;
                uint2 xr = *(const uint2*)(Xsh + t * 68 + sg);
                __nv_bfloat162* xp = (__nv_bfloat162*)&xr;
                float2 f0 = __bfloat1622float2(xp[0]);
                float2 f1 = __bfloat1622float2(xp[1]);
                float4 sv = Sp4[e];
                __nv_bfloat162 h0 = __floats2bfloat162_rn(f0.x + sv.x, f0.y + sv.y);
                __nv_bfloat162 h1 = __floats2bfloat162_rn(f1.x + sv.z, f1.y + sv.w);
                uint2 o; o.x = *(unsigned*)&h0; o.y = *(unsigned*)&h1;
                Bp2[e] = o;
            }
        } else {
            #pragma unroll
            for (int idx = tid; idx < 64 * SUB; idx += 256) {
                int t = idx >> 6, s = idx & 63;
                long gt = tb + t;
                if (gt < T) {
                    float x = __bfloat162float(Xsh[t * 68 + s]) + S[tb * SUB + idx];
                    g_B[tb * SUB + idx] = __float2bfloat16(x);
                }
            }
        }
    }
}

// ---------------------------------------------------------------------------
// k2b: windowed scan — decay over 64 chunks < 1e-19; each warp scans its
// 1024-chunk segment independently after a 2-subtile warm-up.
// ---------------------------------------------------------------------------
__global__ __launch_bounds__(128) void k2b_scan(const float* __restrict__ tausp, int NC)
{
    const int plane = blockIdx.x;               // 0..191
    const int b = plane >> 6, s = plane & 63;
    const int warp = threadIdx.x >> 5, lane = threadIdx.x & 31;

    const float inv = 1.0f / expf(tausp[b]);
    const float dL  = (float)LCH * inv;
    float rho[5], del[5];
    #pragma unroll
    for (int k = 0; k < 5; k++) {
        float off = (float)(1 << k);
        rho[k] = __expf(-off * dL);
        del[k] = off * dL;
    }
    const float pl  = __expf(-(float)lane * dL);
    const float dl  = (float)lane * dL;
    const float r32 = __expf(-32.0f * dL);
    const float rd32 = r32 * 32.0f * dL;        // chain-break constant

    const float2* pln = g_loc[plane];
    const int seg = warp * 1024;
    float cu = 0.f, cv = 0.f;

    #pragma unroll 2
    for (int ti = -2; ti < 32; ti++) {          // 2 warm-up subtiles (64 chunks)
        int c = seg + ti * 32 + lane;
        float2 l = (c >= 0) ? pln[c] : make_float2(0.f, 0.f);

        float au = l.x, av = l.y;
        #pragma unroll
        for (int kk = 0; kk < 5; kk++) {
            int off = 1 << kk;
            float ou = __shfl_up_sync(0xffffffffu, au, off);
            float ov = __shfl_up_sync(0xffffffffu, av, off);
            if (lane >= off) {
                av = fmaf(rho[kk], fmaf(del[kk], ou, ov), av);
                au = fmaf(rho[kk], ou, au);
            }
        }
        float exu = __shfl_up_sync(0xffffffffu, au, 1);
        float exv = __shfl_up_sync(0xffffffffu, av, 1);
        if (lane == 0) { exu = 0.f; exv = 0.f; }

        if (ti >= 0 && c < NC) {
            float su = fmaf(pl, cu, exu);
            float sv = fmaf(pl, fmaf(dl, cu, cv), exv);
            *(float2*)(g_st + ((size_t)c * SUB + s) * 6 + 2 * b) = make_float2(su, sv);
        }
        float iu = __shfl_sync(0xffffffffu, au, 31);
        float iv = __shfl_sync(0xffffffffu, av, 31);
        cv = fmaf(r32, cv, fmaf(rd32, cu, iv));  // 1-FMA cv-chain
        cu = fmaf(r32, cu, iu);
    }
}

// ---------------------------------------------------------------------------
// k2c: main pass. Stages ONLY the 200 live count rows (100 old + 100 new;
// the middle 100 were dead weight). thread = (chunk, s), 25 steps.
// 12.8KB smem + <=42 regs -> 6 blocks/SM.
// ---------------------------------------------------------------------------
__global__ void __launch_bounds__(256, 6) k2c_main(
    const float* __restrict__ Vo, const float* __restrict__ W,
    const float* __restrict__ Ksp, const float* __restrict__ tausp,
    float* __restrict__ out, int T, int NC)
{
    __shared__ __align__(16) uint8_t scnt[SROWS * SUB];   // 12.8KB

    const int tid = threadIdx.x;
    const long tbt = (long)blockIdx.x * (K2CH * LCH);

    // stage live rows: [tbt-200, tbt-100) -> scnt[0:100), [tbt, tbt+100) -> scnt[100:200)
    #pragma unroll
    for (int idx = tid; idx < SROWS * SUB / 16; idx += 256) {
        int row = idx >> 2;
        long g = (row < 100) ? (tbt - THIST + row) : (tbt + row - 100);
        int4 v = make_int4(0, 0, 0, 0);
        if (g >= 0 && g < TCAP)
            v = ((const int4*)(g_zc + g * SUB))[idx & 3];
        ((int4*)scnt)[idx] = v;
    }
    __syncthreads();

    const int cl = tid >> 6, s = tid & 63;
    const int c = blockIdx.x * K2CH + cl;
    if (c >= NC) return;
    const long t0 = (long)c * LCH;
    const int steps = (T - t0 < (long)LCH) ? (int)(T - t0) : LCH;

    float inv0 = 1.0f / expf(tausp[0]);
    float inv1 = 1.0f / expf(tausp[1]);
    float inv2 = 1.0f / expf(tausp[2]);
    float r0 = __expf(-inv0), r1 = __expf(-inv1), r2 = __expf(-inv2);
    float ri0 = r0 * inv0, ri1 = r1 * inv1, ri2 = r2 * inv2;
    float e0 = __expf(-(float)THIST * inv0);
    float e1 = __expf(-(float)THIST * inv1);
    float e2 = __expf(-(float)THIST * inv2);
    float K0 = Ksp[s * 3 + 0], K1 = Ksp[s * 3 + 1], K2 = Ksp[s * 3 + 2];

    const float* pc = g_st + ((size_t)c * SUB + s) * 6;
    float2 a0 = *(const float2*)(pc + 0);
    float2 a1 = *(const float2*)(pc + 2);
    float2 a2 = *(const float2*)(pc + 4);
    float u0c = a0.x, v0c = a0.y, u1c = a1.x, v1c = a1.y, u2c = a2.x, v2c = a2.y;
    float u0o = 0.f, v0o = 0.f, u1o = 0.f, v1o = 0.f, u2o = 0.f, v2o = 0.f;
    if (c >= OLDC) {
        const float* po = g_st + ((size_t)(c - OLDC) * SUB + s) * 6;
        float2 b0 = *(const float2*)(po + 0);
        float2 b1 = *(const float2*)(po + 2);
        float2 b2 = *(const float2*)(po + 4);
        u0o = b0.x; v0o = b0.y; u1o = b1.x; v1o = b1.y; u2o = b2.x; v2o = b2.y;
    }

    const float vo = Vo[0];
    const float ws = W[s];
    const __nv_bfloat16* Bp = g_B + (size_t)t0 * SUB + s;
    float* op = out + (size_t)t0 * SUB + s;
    const uint8_t* cnew = scnt + (100 + cl * LCH) * SUB + s;
    const uint8_t* cold = scnt + (cl * LCH) * SUB + s;

    if (e0 < 1e-8f && e1 < 1e-8f) {
        // Light path: only basis-2 truncation correction is numerically live.
        const float Kq2 = K2 * e2 * (float)THIST * inv2;
        const float Ke2 = K2 * e2;
        #pragma unroll 5
        for (int i = 0; i < steps; i++) {
            float filt = fmaf(K0, v0c, fmaf(K1, v1c, K2 * v2c));
            filt = fmaf(-Kq2, u2o, filt);
            filt = fmaf(-Ke2, v2o, filt);

            float x = __bfloat162float(Bp[(size_t)i * SUB]) + filt;
            float sg = __fdividef(1.0f, 1.0f + __expf(-x));
            op[(size_t)i * SUB] = fmaf(ws, sg, vo);

            float zn = (float)(int)cnew[i * SUB];
            float zo = (float)(int)cold[i * SUB];
            v0c = fmaf(r0, v0c, ri0 * u0c);  u0c = fmaf(r0, u0c, zn);
            v1c = fmaf(r1, v1c, ri1 * u1c);  u1c = fmaf(r1, u1c, zn);
            v2c = fmaf(r2, v2c, ri2 * u2c);  u2c = fmaf(r2, u2c, zn);
            v2o = fmaf(r2, v2o, ri2 * u2o);  u2o = fmaf(r2, u2o, zo);
        }
    } else {
        // Full path (generic taus)
        float q0 = e0 * (float)THIST * inv0;
        float q1 = e1 * (float)THIST * inv1;
        float q2 = e2 * (float)THIST * inv2;
        #pragma unroll 5
        for (int i = 0; i < steps; i++) {
            float tr0 = fmaf(-q0, u0o, v0c); tr0 = fmaf(-e0, v0o, tr0);
            float tr1 = fmaf(-q1, u1o, v1c); tr1 = fmaf(-e1, v1o, tr1);
            float tr2 = fmaf(-q2, u2o, v2c); tr2 = fmaf(-e2, v2o, tr2);
            float filt = fmaf(K0, tr0, fmaf(K1, tr1, K2 * tr2));

            float x = __bfloat162float(Bp[(size_t)i * SUB]) + filt;
            float sg = __fdividef(1.0f, 1.0f + __expf(-x));
            op[(size_t)i * SUB] = fmaf(ws, sg, vo);

            float zn = (float)(int)cnew[i * SUB];
            float zo = (float)(int)cold[i * SUB];
            v0c = fmaf(r0, v0c, ri0 * u0c);  u0c = fmaf(r0, u0c, zn);
            v0o = fmaf(r0, v0o, ri0 * u0o);  u0o = fmaf(r0, u0o, zo);
            v1c = fmaf(r1, v1c, ri1 * u1c);  u1c = fmaf(r1, u1c, zn);
            v1o = fmaf(r1, v1o, ri1 * u1o);  u1o = fmaf(r1, u1o, zo);
            v2c = fmaf(r2, v2c, ri2 * u2c);  u2c = fmaf(r2, u2c, zn);
            v2o = fmaf(r2, v2o, ri2 * u2o);  u2o = fmaf(r2, u2o, zo);
        }
    }
}

// ---------------------------------------------------------------------------
extern "C" void kernel_launch(void* const* d_in, const int* in_sizes, int n_in,
                              void* d_out, int out_size)
{
    const float* S     = (const float*)d_in[0];
    const float* Y     = (const float*)d_in[1];
    const float* Z     = (const float*)d_in[2];
    const float* C     = (const float*)d_in[3];
    const float* Vo    = (const float*)d_in[4];
    const float* W     = (const float*)d_in[5];
    const float* theta = (const float*)d_in[6];
    const float* Ksp   = (const float*)d_in[7];
    const float* tausp = (const float*)d_in[8];
    float* out = (float*)d_out;

    int T = in_sizes[0] / SUB;
    if (T > TCAP) T = TCAP;
    const int NC = (T + LCH - 1) / LCH;

    const int gA = (T + 99) / 100;
    const int gB = (T + 63) / 64;
    kA_combined<<<gA + gB, 256>>>(S, Y, Z, C, theta, tausp, T, NC, gA);

    k2b_scan<<<3 * SUB, 128>>>(tausp, NC);

    const int gC = (NC + K2CH - 1) / K2CH;
    k2c_main<<<gC, 256>>>(Vo, W, Ksp, tausp, out, T, NC);
}

// round 16
// speedup vs baseline: 1.5913x; 1.0857x over previous
#include <cuda_runtime.h>
#include <cuda_bf16.h>
#include <stdint.h>

// Fixed dataset: SUB_NO=64, T_HIST=200, T_DATA=100000, delta_spike=0
#define SUB    64
#define THIST  200
#define LCH    25                 // chunk length; divides THIST
#define OLDC   (THIST / LCH)      // 8 chunks back = t-200
#define NCPAD  4096               // padded chunk capacity (4 warp segments of 1024)
#define TCAP   (NCPAD * LCH)      // 102400
#define K2CH   4                  // chunks per k2c block (100 t rows)
#define SROWS  200                // staged count rows: 100 old + 100 new (live only)

// Device scratch (zero-initialized at module load; never freed)
__device__ __align__(16) uint8_t g_zc[(size_t)TCAP * SUB];   // spike counts Zc[t][s]
__device__ __align__(16) __nv_bfloat16 g_B[(size_t)TCAP * SUB]; // S + theta + Y@C^T (bf16)
__device__ float2          g_loc[3 * SUB][NCPAD];            // [b*64+s][c] local (Lu,Lv)
__device__ float           g_st[(size_t)NCPAD * SUB * 6];    // [c][s][b*2] exclusive (u,v)

// ---------------------------------------------------------------------------
// kA (block-specialized): blocks [0,gA) run branch A (spike side), blocks
// [gA, gA+gB) run branch B (B-matrix side). Disjoint inputs, overlapped SMs.
// (FROZEN from R15 — best measured.)
// ---------------------------------------------------------------------------
__global__ void __launch_bounds__(256, 6) kA_combined(
    const float* __restrict__ S, const float* __restrict__ Y,
    const float* __restrict__ Z, const float* __restrict__ C,
    const float* __restrict__ theta, const float* __restrict__ tausp,
    int T, int NC, int gA)
{
    __shared__ __align__(16) char smbuf[30720];

    const int tid = threadIdx.x, lane = tid & 31, warp = tid >> 5;

    if ((int)blockIdx.x < gA) {
        // ================= Branch A: spike side =================
        uint64_t* msh   = (uint64_t*)(smbuf);                // 104*8 = 832
        uint64_t* CmA   = (uint64_t*)(smbuf + 832);          // 64*8 = 512
        float2  (*shloc)[4] = (float2(*)[4])(smbuf + 1344);  // 192*4*8 = 6144
        float*   s_cst  = (float*)(smbuf + 7488);            // 9 floats

        const long tb = (long)blockIdx.x * 100;

        // permuted C masks via float2 ballots (warp sweeps one C row)
        #pragma unroll
        for (int ss = 0; ss < 8; ss++) {
            int s = warp * 8 + ss;
            float2 cv = ((const float2*)(C + s * SUB))[lane];
            unsigned m0 = __ballot_sync(0xffffffffu, cv.x != 0.f);  // subunits 2k
            unsigned m1 = __ballot_sync(0xffffffffu, cv.y != 0.f);  // subunits 2k+1
            if (lane == 0) CmA[s] = (uint64_t)m0 | ((uint64_t)m1 << 32);
        }
        // pack Z rows (permuted bit order matching CmA)
        #pragma unroll
        for (int rr = 0; rr < 13; rr++) {
            int t = warp * 13 + rr;
            long gt = tb + t;
            bool valid = (t < 100) && (gt < T);
            float2 z = make_float2(0.f, 0.f);
            if (valid) z = ((const float2*)(Z + gt * SUB))[lane];
            unsigned m0 = __ballot_sync(0xffffffffu, z.x != 0.f);
            unsigned m1 = __ballot_sync(0xffffffffu, z.y != 0.f);
            if (lane == 0 && t < 100)
                msh[t] = (uint64_t)m0 | ((uint64_t)m1 << 32);
        }
        if (tid < 3) {
            float inv = 1.0f / expf(tausp[tid]);
            float r   = __expf(-inv);
            s_cst[tid]     = inv;
            s_cst[3 + tid] = r;
            s_cst[6 + tid] = r * inv;      // chain-break constant
        }
        __syncthreads();

        // locals + direct count stores: thread = (chunk-in-block, s)
        {
            const int cl = tid >> 6, s = tid & 63;
            const uint64_t cm = CmA[s];
            const float r0 = s_cst[3], r1 = s_cst[4], r2 = s_cst[5];
            const float ri0 = s_cst[6], ri1 = s_cst[7], ri2 = s_cst[8];

            float w0 = 1.f, w1 = 1.f, w2 = 1.f;
            float y0 = 0.f, y1 = 0.f, y2 = 0.f;
            float lu0=0.f,lu1=0.f,lu2=0.f, lv0=0.f,lv1=0.f,lv2=0.f;
            const int rbase = cl * LCH + (LCH - 1);
            uint8_t* zcp = g_zc + (tb + rbase) * SUB + s;
            #pragma unroll
            for (int j = 0; j < LCH; j++) {
                int row = rbase - j;
                int cnti = __popcll(msh[row] & cm);
                zcp[-(long)j * SUB] = (uint8_t)cnti;   // coalesced STG.U8
                float cnt = (float)cnti;
                lu0 = fmaf(w0, cnt, lu0);  lv0 = fmaf(y0, cnt, lv0);
                lu1 = fmaf(w1, cnt, lu1);  lv1 = fmaf(y1, cnt, lv1);
                lu2 = fmaf(w2, cnt, lu2);  lv2 = fmaf(y2, cnt, lv2);
                y0 = fmaf(r0, y0, ri0 * w0);  w0 *= r0;   // 1-FMA y-chain
                y1 = fmaf(r1, y1, ri1 * w1);  w1 *= r1;
                y2 = fmaf(r2, y2, ri2 * w2);  w2 *= r2;
            }
            shloc[s][cl]           = make_float2(lu0, lv0);
            shloc[SUB + s][cl]     = make_float2(lu1, lv1);
            shloc[2 * SUB + s][cl] = make_float2(lu2, lv2);
        }
        __syncthreads();

        if (tid < 3 * SUB) {
            #pragma unroll
            for (int k = 0; k < 4; k++) {
                int cc = blockIdx.x * 4 + k;
                if (cc < NC) g_loc[tid][cc] = shloc[tid][k];
            }
        }
    } else {
        // ================= Branch B: B-matrix side =================
        float*          Ysh  = (float*)(smbuf);                  // 64*65*4 = 16640
        __nv_bfloat16*  Xsh  = (__nv_bfloat16*)(smbuf + 16640);  // 64*68*2 = 8704
        uint64_t*       CmB  = (uint64_t*)(smbuf + 25344);       // 512
        uint8_t*        idxs = (uint8_t*)(smbuf + 25856);        // 64*68 = 4352
        int*            cnt4 = (int*)(smbuf + 30208);            // 256

        const long tb = (long)(blockIdx.x - gA) * 64;

        // unpermuted C masks via scalar ballots
        #pragma unroll
        for (int ss = 0; ss < 8; ss++) {
            int s = warp * 8 + ss;
            float c0 = C[s * SUB + lane];
            float c1 = C[s * SUB + 32 + lane];
            unsigned m0 = __ballot_sync(0xffffffffu, c0 != 0.f);
            unsigned m1 = __ballot_sync(0xffffffffu, c1 != 0.f);
            if (lane == 0) CmB[s] = (uint64_t)m0 | ((uint64_t)m1 << 32);
        }
        // stage Y tile (coalesced) + zero the dummy column 64
        #pragma unroll
        for (int idx = tid; idx < 64 * SUB; idx += 256) {
            int t = idx >> 6;
            long gt = tb + t;
            Ysh[t * 65 + (idx & 63)] = (gt < T) ? Y[tb * SUB + idx] : 0.f;
        }
        if (tid < 64) Ysh[tid * 65 + 64] = 0.f;
        __syncthreads();

        // Build per-s index lists (once per block), padded to quads with 64.
        if (tid < SUB) {
            uint64_t m = CmB[tid];
            uint8_t* ip = idxs + tid * 68;
            int k = 0;
            while (m) {
                ip[k++] = (uint8_t)(__ffsll((long long)m) - 1);
                m &= m - 1;
            }
            while (k & 3) ip[k++] = 64;    // dummy -> zero column
            cnt4[tid] = k;
        }
        __syncthreads();

        // Quad-index gather: warp per s, lanes = t, BOTH halves per index.
        #pragma unroll
        for (int uu = 0; uu < 8; uu++) {
            int s = uu * 8 + warp;
            float th = __ldg(theta + s);
            float acc0 = th, acc1 = th;
            const uint8_t* ip = idxs + s * 68;
            const int n4 = cnt4[s];
            const int base0 = lane * 65;
            const int base1 = (lane + 32) * 65;
            for (int k = 0; k < n4; k += 4) {
                uchar4 j4 = *(const uchar4*)(ip + k);   // broadcast LDS.U32
                acc0 += Ysh[base0 + j4.x];  acc1 += Ysh[base1 + j4.x];
                acc0 += Ysh[base0 + j4.y];  acc1 += Ysh[base1 + j4.y];
                acc0 += Ysh[base0 + j4.z];  acc1 += Ysh[base1 + j4.z];
                acc0 += Ysh[base0 + j4.w];  acc1 += Ysh[base1 + j4.w];
            }
            Xsh[lane * 68 + s]        = __float2bfloat16(acc0);
            Xsh[(lane + 32) * 68 + s] = __float2bfloat16(acc1);
        }
        __syncthreads();

        // B = raw + theta + S, bf16. Vectorized x4 (stride-68 Xsh keeps
        // 8B alignment for all t).
        if (tb + 64 <= T) {
            const float4* Sp4 = (const float4*)(S + tb * SUB);
            uint2* Bp2 = (uint2*)(g_B + tb * SUB);
            #pragma unroll
            for (int e = tid; e < 64 * SUB / 4; e += 256) {
                int t = e >> 4, sg = (e & 15) * 4;
                uint2 xr = *(const uint2*)(Xsh + t * 68 + sg);
                __nv_bfloat162* xp = (__nv_bfloat162*)&xr;
                float2 f0 = __bfloat1622float2(xp[0]);
                float2 f1 = __bfloat1622float2(xp[1]);
                float4 sv = Sp4[e];
                __nv_bfloat162 h0 = __floats2bfloat162_rn(f0.x + sv.x, f0.y + sv.y);
                __nv_bfloat162 h1 = __floats2bfloat162_rn(f1.x + sv.z, f1.y + sv.w);
                uint2 o; o.x = *(unsigned*)&h0; o.y = *(unsigned*)&h1;
                Bp2[e] = o;
            }
        } else {
            #pragma unroll
            for (int idx = tid; idx < 64 * SUB; idx += 256) {
                int t = idx >> 6, s = idx & 63;
                long gt = tb + t;
                if (gt < T) {
                    float x = __bfloat162float(Xsh[t * 68 + s]) + S[tb * SUB + idx];
                    g_B[tb * SUB + idx] = __float2bfloat16(x);
                }
            }
        }
    }
}

// ---------------------------------------------------------------------------
// k2b: windowed scan — decay over 64 chunks < 1e-19; each warp scans its
// 1024-chunk segment independently after a 2-subtile warm-up. (FROZEN.)
// ---------------------------------------------------------------------------
__global__ __launch_bounds__(128) void k2b_scan(const float* __restrict__ tausp, int NC)
{
    const int plane = blockIdx.x;               // 0..191
    const int b = plane >> 6, s = plane & 63;
    const int warp = threadIdx.x >> 5, lane = threadIdx.x & 31;

    const float inv = 1.0f / expf(tausp[b]);
    const float dL  = (float)LCH * inv;
    float rho[5], del[5];
    #pragma unroll
    for (int k = 0; k < 5; k++) {
        float off = (float)(1 << k);
        rho[k] = __expf(-off * dL);
        del[k] = off * dL;
    }
    const float pl  = __expf(-(float)lane * dL);
    const float dl  = (float)lane * dL;
    const float r32 = __expf(-32.0f * dL);
    const float rd32 = r32 * 32.0f * dL;        // chain-break constant

    const float2* pln = g_loc[plane];
    const int seg = warp * 1024;
    float cu = 0.f, cv = 0.f;

    #pragma unroll 2
    for (int ti = -2; ti < 32; ti++) {          // 2 warm-up subtiles (64 chunks)
        int c = seg + ti * 32 + lane;
        float2 l = (c >= 0) ? pln[c] : make_float2(0.f, 0.f);

        float au = l.x, av = l.y;
        #pragma unroll
        for (int kk = 0; kk < 5; kk++) {
            int off = 1 << kk;
            float ou = __shfl_up_sync(0xffffffffu, au, off);
            float ov = __shfl_up_sync(0xffffffffu, av, off);
            if (lane >= off) {
                av = fmaf(rho[kk], fmaf(del[kk], ou, ov), av);
                au = fmaf(rho[kk], ou, au);
            }
        }
        float exu = __shfl_up_sync(0xffffffffu, au, 1);
        float exv = __shfl_up_sync(0xffffffffu, av, 1);
        if (lane == 0) { exu = 0.f; exv = 0.f; }

        if (ti >= 0 && c < NC) {
            float su = fmaf(pl, cu, exu);
            float sv = fmaf(pl, fmaf(dl, cu, cv), exv);
            *(float2*)(g_st + ((size_t)c * SUB + s) * 6 + 2 * b) = make_float2(su, sv);
        }
        float iu = __shfl_sync(0xffffffffu, au, 31);
        float iv = __shfl_sync(0xffffffffu, av, 31);
        cv = fmaf(r32, cv, fmaf(rd32, cu, iv));  // 1-FMA cv-chain
        cu = fmaf(r32, cu, iu);
    }
}

// ---------------------------------------------------------------------------
// k2c: main pass. Stages the 200 live count rows AND the block's 100-row
// B tile into shared (both as int4) — the hot loop touches global memory
// only for the output store. 25.6KB smem + <=42 regs -> 6 blocks/SM.
// ---------------------------------------------------------------------------
__global__ void __launch_bounds__(256, 6) k2c_main(
    const float* __restrict__ Vo, const float* __restrict__ W,
    const float* __restrict__ Ksp, const float* __restrict__ tausp,
    float* __restrict__ out, int T, int NC)
{
    __shared__ __align__(16) uint8_t scnt[SROWS * SUB];        // 12.8KB
    __shared__ __align__(16) __nv_bfloat16 sB[100 * SUB];      // 12.8KB

    const int tid = threadIdx.x;
    const long tbt = (long)blockIdx.x * (K2CH * LCH);

    // stage live count rows: [tbt-200, tbt-100) -> scnt[0:100),
    //                        [tbt,     tbt+100) -> scnt[100:200)
    #pragma unroll
    for (int idx = tid; idx < SROWS * SUB / 16; idx += 256) {
        int row = idx >> 2;
        long g = (row < 100) ? (tbt - THIST + row) : (tbt + row - 100);
        int4 v = make_int4(0, 0, 0, 0);
        if (g >= 0 && g < TCAP)
            v = ((const int4*)(g_zc + g * SUB))[idx & 3];
        ((int4*)scnt)[idx] = v;
    }
    // stage B tile [tbt, tbt+100) as int4 (rows beyond T are unread)
    {
        const int4* gB4 = (const int4*)(g_B + tbt * SUB);
        #pragma unroll
        for (int idx = tid; idx < 100 * SUB * 2 / 16; idx += 256)
            ((int4*)sB)[idx] = gB4[idx];
    }
    __syncthreads();

    const int cl = tid >> 6, s = tid & 63;
    const int c = blockIdx.x * K2CH + cl;
    if (c >= NC) return;
    const long t0 = (long)c * LCH;
    const int steps = (T - t0 < (long)LCH) ? (int)(T - t0) : LCH;

    float inv0 = 1.0f / expf(tausp[0]);
    float inv1 = 1.0f / expf(tausp[1]);
    float inv2 = 1.0f / expf(tausp[2]);
    float r0 = __expf(-inv0), r1 = __expf(-inv1), r2 = __expf(-inv2);
    float ri0 = r0 * inv0, ri1 = r1 * inv1, ri2 = r2 * inv2;
    float e0 = __expf(-(float)THIST * inv0);
    float e1 = __expf(-(float)THIST * inv1);
    float e2 = __expf(-(float)THIST * inv2);
    float K0 = Ksp[s * 3 + 0], K1 = Ksp[s * 3 + 1], K2 = Ksp[s * 3 + 2];

    const float* pc = g_st + ((size_t)c * SUB + s) * 6;
    float2 a0 = *(const float2*)(pc + 0);
    float2 a1 = *(const float2*)(pc + 2);
    float2 a2 = *(const float2*)(pc + 4);
    float u0c = a0.x, v0c = a0.y, u1c = a1.x, v1c = a1.y, u2c = a2.x, v2c = a2.y;
    float u0o = 0.f, v0o = 0.f, u1o = 0.f, v1o = 0.f, u2o = 0.f, v2o = 0.f;
    if (c >= OLDC) {
        const float* po = g_st + ((size_t)(c - OLDC) * SUB + s) * 6;
        float2 b0 = *(const float2*)(po + 0);
        float2 b1 = *(const float2*)(po + 2);
        float2 b2 = *(const float2*)(po + 4);
        u0o = b0.x; v0o = b0.y; u1o = b1.x; v1o = b1.y; u2o = b2.x; v2o = b2.y;
    }

    const float vo = Vo[0];
    const float ws = W[s];
    const __nv_bfloat16* Bp = sB + (cl * LCH) * SUB + s;      // shared now
    float* op = out + (size_t)t0 * SUB + s;
    const uint8_t* cnew = scnt + (100 + cl * LCH) * SUB + s;
    const uint8_t* cold = scnt + (cl * LCH) * SUB + s;

    if (e0 < 1e-8f && e1 < 1e-8f) {
        // Light path: only basis-2 truncation correction is numerically live.
        const float Kq2 = K2 * e2 * (float)THIST * inv2;
        const float Ke2 = K2 * e2;

        #define K2C_STEP(i)                                                         \
        {                                                                           \
            float filt = fmaf(K0, v0c, fmaf(K1, v1c, K2 * v2c));                    \
            filt = fmaf(-Kq2, u2o, filt);                                           \
            filt = fmaf(-Ke2, v2o, filt);                                           \
            float x = __bfloat162float(Bp[(i) * SUB]) + filt;                       \
            float sg = __fdividef(1.0f, 1.0f + __expf(-x));                         \
            op[(size_t)(i) * SUB] = fmaf(ws, sg, vo);                               \
            float zn = (float)(int)cnew[(i) * SUB];                                 \
            float zo = (float)(int)cold[(i) * SUB];                                 \
            v0c = fmaf(r0, v0c, ri0 * u0c);  u0c = fmaf(r0, u0c, zn);               \
            v1c = fmaf(r1, v1c, ri1 * u1c);  u1c = fmaf(r1, u1c, zn);               \
            v2c = fmaf(r2, v2c, ri2 * u2c);  u2c = fmaf(r2, u2c, zn);               \
            v2o = fmaf(r2, v2o, ri2 * u2o);  u2o = fmaf(r2, u2o, zo);               \
        }

        if (steps == LCH) {
            #pragma unroll
            for (int i = 0; i < LCH; i++) K2C_STEP(i)
        } else {
            for (int i = 0; i < steps; i++) K2C_STEP(i)
        }
        #undef K2C_STEP
    } else {
        // Full path (generic taus)
        float q0 = e0 * (float)THIST * inv0;
        float q1 = e1 * (float)THIST * inv1;
        float q2 = e2 * (float)THIST * inv2;
        for (int i = 0; i < steps; i++) {
            float tr0 = fmaf(-q0, u0o, v0c); tr0 = fmaf(-e0, v0o, tr0);
            float tr1 = fmaf(-q1, u1o, v1c); tr1 = fmaf(-e1, v1o, tr1);
            float tr2 = fmaf(-q2, u2o, v2c); tr2 = fmaf(-e2, v2o, tr2);
            float filt = fmaf(K0, tr0, fmaf(K1, tr1, K2 * tr2));

            float x = __bfloat162float(Bp[i * SUB]) + filt;
            float sg = __fdividef(1.0f, 1.0f + __expf(-x));
            op[(size_t)i * SUB] = fmaf(ws, sg, vo);

            float zn = (float)(int)cnew[i * SUB];
            float zo = (float)(int)cold[i * SUB];
            v0c = fmaf(r0, v0c, ri0 * u0c);  u0c = fmaf(r0, u0c, zn);
            v0o = fmaf(r0, v0o, ri0 * u0o);  u0o = fmaf(r0, u0o, zo);
            v1c = fmaf(r1, v1c, ri1 * u1c);  u1c = fmaf(r1, u1c, zn);
            v1o = fmaf(r1, v1o, ri1 * u1o);  u1o = fmaf(r1, u1o, zo);
            v2c = fmaf(r2, v2c, ri2 * u2c);  u2c = fmaf(r2, u2c, zn);
            v2o = fmaf(r2, v2o, ri2 * u2o);  u2o = fmaf(r2, u2o, zo);
        }
    }
}

// ---------------------------------------------------------------------------
extern "C" void kernel_launch(void* const* d_in, const int* in_sizes, int n_in,
                              void* d_out, int out_size)
{
    const float* S     = (const float*)d_in[0];
    const float* Y     = (const float*)d_in[1];
    const float* Z     = (const float*)d_in[2];
    const float* C     = (const float*)d_in[3];
    const float* Vo    = (const float*)d_in[4];
    const float* W     = (const float*)d_in[5];
    const float* theta = (const float*)d_in[6];
    const float* Ksp   = (const float*)d_in[7];
    const float* tausp = (const float*)d_in[8];
    float* out = (float*)d_out;

    int T = in_sizes[0] / SUB;
    if (T > TCAP) T = TCAP;
    const int NC = (T + LCH - 1) / LCH;

    const int gA = (T + 99) / 100;
    const int gB = (T + 63) / 64;
    kA_combined<<<gA + gB, 256>>>(S, Y, Z, C, theta, tausp, T, NC, gA);

    k2b_scan<<<3 * SUB, 128>>>(tausp, NC);

    const int gC = (NC + K2CH - 1) / K2CH;
    k2c_main<<<gC, 256>>>(Vo, W, Ksp, tausp, out, T, NC);
}